// round 6
// baseline (speedup 1.0000x reference)
#include <cuda_runtime.h>
#include <cuda_bf16.h>
#include <stdint.h>
#include <math.h>

typedef unsigned int u32;

#define TOKENS 4096
#define DIM    1024
#define QKV_N  3072
#define NH     16
#define HD     64
#define TSEQ   2048
#define BHEADS 32
#define ATT_SCALE 0.125f

// ---------------- global scratch ----------------
__device__ float g_q[BHEADS * TSEQ * HD];   // [bh][t][d]
__device__ float g_k[BHEADS * TSEQ * HD];
__device__ float g_v[BHEADS * TSEQ * HD];
__device__ float g_o[TOKENS * DIM];         // token-major

// bf16 hi/lo packed (pairs along K)
__device__ u32 g_xh[TOKENS * DIM / 2],  g_xl[TOKENS * DIM / 2];
__device__ u32 g_oh[TOKENS * DIM / 2],  g_ol[TOKENS * DIM / 2];
__device__ u32 g_wqh[QKV_N * DIM / 2],  g_wql[QKV_N * DIM / 2];   // [n][k2]
__device__ u32 g_wph[DIM * DIM / 2],    g_wpl[DIM * DIM / 2];     // [n][k2]

// ---------------- helpers ----------------
__device__ __forceinline__ void mma_bf16(float c[4],
                                         const u32 a[4], const u32 b[2])
{
    asm volatile(
        "mma.sync.aligned.m16n8k16.row.col.f32.bf16.bf16.f32 "
        "{%0,%1,%2,%3}, {%4,%5,%6,%7}, {%8,%9}, {%0,%1,%2,%3};"
        : "+f"(c[0]), "+f"(c[1]), "+f"(c[2]), "+f"(c[3])
        : "r"(a[0]), "r"(a[1]), "r"(a[2]), "r"(a[3]),
          "r"(b[0]), "r"(b[1]));
}

__device__ __forceinline__ void split_pack(float x0, float x1,
                                           u32& hi, u32& lo)
{
    __nv_bfloat162 H = __floats2bfloat162_rn(x0, x1);
    float2 hf = __bfloat1622float2(H);
    __nv_bfloat162 L = __floats2bfloat162_rn(x0 - hf.x, x1 - hf.y);
    hi = *(u32*)&H;
    lo = *(u32*)&L;
}

__device__ __forceinline__ void cp16(u32* dst, const u32* src)
{
    unsigned d = (unsigned)__cvta_generic_to_shared(dst);
    asm volatile("cp.async.cg.shared.global [%0], [%1], 16;" :: "r"(d), "l"(src));
}

// ---------------- prepass: row split (pairs along row dim) ----------------
__global__ __launch_bounds__(256)
void split_rows(const float* __restrict__ src, u32* __restrict__ hi,
                u32* __restrict__ lo, int npairs)
{
    int i = blockIdx.x * 256 + threadIdx.x;
    if (i >= npairs) return;
    float2 v = ((const float2*)src)[i];
    split_pack(v.x, v.y, hi[i], lo[i]);
}

// ---------------- prepass: transpose + split B[K][N] -> BpT[n][k2] ----------
__global__ __launch_bounds__(256)
void transpose_split(const float* __restrict__ B, u32* __restrict__ hiT,
                     u32* __restrict__ loT, int N, int K)
{
    __shared__ float sm[64][33];
    const int k0 = blockIdx.y * 64, n0 = blockIdx.x * 32;
    const int tid = threadIdx.x;
    const int ln = tid & 31, wr = tid >> 5;
    #pragma unroll
    for (int i = 0; i < 8; i++)
        sm[wr + i * 8][ln] = B[(size_t)(k0 + wr + i * 8) * N + n0 + ln];
    __syncthreads();
    const int k2l = tid & 31;
    const int K2 = K >> 1;
    #pragma unroll
    for (int j = 0; j < 4; j++) {
        int nl = (tid >> 5) * 4 + j;
        u32 h, l;
        split_pack(sm[2 * k2l][nl], sm[2 * k2l + 1][nl], h, l);
        size_t o = (size_t)(n0 + nl) * K2 + (k0 >> 1) + k2l;
        hiT[o] = h;
        loT[o] = l;
    }
}

// ---------------------------------------------------------------------------
// mma_gemm2: bf16x3 split GEMM, pre-split operands, cp.async 2-stage pipeline.
// A: [M][K2] pairs (hi/lo). B: [N][K2] pairs (hi/lo).
// Tile 128x128, BK=32 (16 pairs), 256 threads, 8 warps of 64x32.
// epi=0: C=A@B+bias. epi=1: scatter into g_q/g_k/g_v.
// smem: 4 arrays x 2 stages x 128 rows x 20 u32 = 80KB dynamic.
// ---------------------------------------------------------------------------
#define ST_SZ   (128 * 20)           // u32 per array per stage
#define G2_SMEM (4 * 2 * ST_SZ * 4)  // bytes = 81920

__global__ __launch_bounds__(256, 2)
void mma_gemm2(const u32* __restrict__ Agh, const u32* __restrict__ Agl,
               const u32* __restrict__ Bgh, const u32* __restrict__ Bgl,
               float* __restrict__ C, const float* __restrict__ bias,
               int N, int K, int epi)
{
    extern __shared__ u32 sm[];
    u32* AsH = sm;
    u32* AsL = AsH + 2 * ST_SZ;
    u32* BsH = AsL + 2 * ST_SZ;
    u32* BsL = BsH + 2 * ST_SZ;

    const int tid  = threadIdx.x;
    const int wid  = tid >> 5;
    const int lane = tid & 31;
    const int r8   = lane >> 2;
    const int c4   = lane & 3;
    const int wm   = (wid >> 2) * 64;
    const int wn   = (wid & 3) * 32;
    const int brow = blockIdx.y, bcol = blockIdx.x;
    const int K2   = K >> 1;

    // copy mapping: row cr (0..127), chunk base ch (0 or 2)
    const int cr = tid & 127;
    const int ch = (tid >> 7) * 2;

    const u32* Aph = Agh + (size_t)(brow * 128 + cr) * K2;
    const u32* Apl = Agl + (size_t)(brow * 128 + cr) * K2;
    const u32* Bph = Bgh + (size_t)(bcol * 128 + cr) * K2;
    const u32* Bpl = Bgl + (size_t)(bcol * 128 + cr) * K2;

    float acc[4][4][4];
    #pragma unroll
    for (int i = 0; i < 4; i++)
        #pragma unroll
        for (int j = 0; j < 4; j++)
            #pragma unroll
            for (int r = 0; r < 4; r++) acc[i][j][r] = 0.f;

    auto issue = [&](int kp, int s) {
        u32* base = sm;
        const int off = s * ST_SZ + cr * 20;
        #pragma unroll
        for (int c = 0; c < 2; c++) {
            const int cc = (ch + c) * 4;
            cp16(AsH + off + cc, Aph + kp + cc);
            cp16(AsL + off + cc, Apl + kp + cc);
            cp16(BsH + off + cc, Bph + kp + cc);
            cp16(BsL + off + cc, Bpl + kp + cc);
        }
        (void)base;
        asm volatile("cp.async.commit_group;");
    };

    issue(0, 0);
    issue(16, 1);

    const int nst = K >> 5;
    for (int ks = 0; ks < nst; ks++) {
        asm volatile("cp.async.wait_group 1;");
        __syncthreads();
        const int s = ks & 1;
        const u32* aH = AsH + s * ST_SZ;
        const u32* aL = AsL + s * ST_SZ;
        const u32* bH = BsH + s * ST_SZ;
        const u32* bL = BsL + s * ST_SZ;

        #pragma unroll
        for (int kk = 0; kk < 2; kk++) {
            u32 bh[4][2], bl[4][2];
            #pragma unroll
            for (int nf = 0; nf < 4; nf++) {
                const int n = wn + nf * 8 + r8;
                bh[nf][0] = bH[n * 20 + kk * 8 + c4];
                bh[nf][1] = bH[n * 20 + kk * 8 + c4 + 4];
                bl[nf][0] = bL[n * 20 + kk * 8 + c4];
                bl[nf][1] = bL[n * 20 + kk * 8 + c4 + 4];
            }
            #pragma unroll
            for (int mf = 0; mf < 4; mf++) {
                const int m = wm + mf * 16 + r8;
                u32 ah[4], al[4];
                ah[0] = aH[m * 20 + kk * 8 + c4];
                ah[1] = aH[(m + 8) * 20 + kk * 8 + c4];
                ah[2] = aH[m * 20 + kk * 8 + c4 + 4];
                ah[3] = aH[(m + 8) * 20 + kk * 8 + c4 + 4];
                al[0] = aL[m * 20 + kk * 8 + c4];
                al[1] = aL[(m + 8) * 20 + kk * 8 + c4];
                al[2] = aL[m * 20 + kk * 8 + c4 + 4];
                al[3] = aL[(m + 8) * 20 + kk * 8 + c4 + 4];
                #pragma unroll
                for (int nf = 0; nf < 4; nf++) {
                    mma_bf16(acc[mf][nf], ah, bh[nf]);
                    mma_bf16(acc[mf][nf], ah, bl[nf]);
                    mma_bf16(acc[mf][nf], al, bh[nf]);
                }
            }
        }
        __syncthreads();
        if (ks + 2 < nst) {
            issue((ks + 2) * 16, s);
        } else {
            asm volatile("cp.async.commit_group;");
        }
    }

    // epilogue
    if (!epi) {
        #pragma unroll
        for (int nf = 0; nf < 4; nf++) {
            const int cg = bcol * 128 + wn + nf * 8 + c4 * 2;
            float bx = bias ? bias[cg]     : 0.f;
            float by = bias ? bias[cg + 1] : 0.f;
            #pragma unroll
            for (int mf = 0; mf < 4; mf++) {
                const int rg = brow * 128 + wm + mf * 16 + r8;
                float2 v0 = make_float2(acc[mf][nf][0] + bx, acc[mf][nf][1] + by);
                float2 v1 = make_float2(acc[mf][nf][2] + bx, acc[mf][nf][3] + by);
                *(float2*)(C + (size_t)rg * N + cg)       = v0;
                *(float2*)(C + (size_t)(rg + 8) * N + cg) = v1;
            }
        }
    } else {
        #pragma unroll
        for (int nf = 0; nf < 4; nf++) {
            const int n_g   = bcol * 128 + wn + nf * 8 + c4 * 2;
            const int which = n_g >> 10;        // 0=q 1=k 2=v
            const int rmod  = n_g & 1023;
            const int h     = rmod >> 6;
            const int d     = rmod & 63;
            float* base = (which == 0) ? g_q : (which == 1) ? g_k : g_v;
            #pragma unroll
            for (int mf = 0; mf < 4; mf++) {
                const int m_g0 = brow * 128 + wm + mf * 16 + r8;
                #pragma unroll
                for (int half = 0; half < 2; half++) {
                    const int m_g = m_g0 + half * 8;
                    const int b   = m_g >> 11;
                    const int t   = m_g & 2047;
                    float2 v = make_float2(acc[mf][nf][half * 2],
                                           acc[mf][nf][half * 2 + 1]);
                    *(float2*)(base + (((size_t)(b * 16 + h) * TSEQ + t) * HD + d)) = v;
                }
            }
        }
    }
}

// ---------------------------------------------------------------------------
// In-place RoPE on g_q and g_k. One warp per (bh, t).
// ---------------------------------------------------------------------------
__global__ __launch_bounds__(256)
void rope_inplace()
{
    int gw   = (blockIdx.x * blockDim.x + threadIdx.x) >> 5;
    int lane = threadIdx.x & 31;
    if (gw >= BHEADS * TSEQ) return;
    int bh = gw >> 11;
    int t  = gw & 2047;

    float freq = expf(-9.210340371976184f * (float)lane * (1.0f / 32.0f));
    float ang  = (float)t * freq;
    float s, c;
    sincosf(ang, &s, &c);

    size_t off = ((size_t)bh * TSEQ + t) * HD;

    float q1 = g_q[off + lane], q2 = g_q[off + lane + 32];
    g_q[off + lane]      = q1 * c - q2 * s;
    g_q[off + lane + 32] = q1 * s + q2 * c;

    float k1 = g_k[off + lane], k2 = g_k[off + lane + 32];
    g_k[off + lane]      = k1 * c - k2 * s;
    g_k[off + lane + 32] = k1 * s + k2 * c;
}

// ---------------------------------------------------------------------------
// Flash attention: BQ=128, BK=64, 256 threads (fp32).
// ---------------------------------------------------------------------------
#define FA_BQ 128
#define FA_BK 64
#define PSS   68

#define FA_SMEM_FLOATS (64*128 + 64*64 + 64*64 + 128*PSS)

extern __shared__ float fa_smem[];

__global__ __launch_bounds__(256)
void flash_attn2()
{
    float* Qs = fa_smem;             // [d][r]  64 x 128
    float* Ks = Qs + 64 * 128;       // [d][j]  64 x 64
    float* Vs = Ks + 64 * 64;        // [j][d]  64 x 64
    float* Ps = Vs + 64 * 64;        // [r][j]  128 x PSS

    const int bh   = blockIdx.y;
    const int qblk = gridDim.x - 1 - blockIdx.x;
    const int q0   = qblk * FA_BQ;

    const float* Qh = g_q + (size_t)bh * TSEQ * HD;
    const float* Kh = g_k + (size_t)bh * TSEQ * HD;
    const float* Vh = g_v + (size_t)bh * TSEQ * HD;

    const int tid = threadIdx.x;
    const int tr  = tid >> 4;
    const int tc  = tid & 15;

    {
        int r     = tid >> 1;
        int dbase = (tid & 1) * 32;
        const float* qp = Qh + (size_t)(q0 + r) * HD + dbase;
        #pragma unroll
        for (int j = 0; j < 32; j += 4) {
            float4 v = *(const float4*)(qp + j);
            Qs[(dbase + j + 0) * 128 + r] = v.x;
            Qs[(dbase + j + 1) * 128 + r] = v.y;
            Qs[(dbase + j + 2) * 128 + r] = v.z;
            Qs[(dbase + j + 3) * 128 + r] = v.w;
        }
    }

    float oacc[8][4];
    float m[8], l[8];
    #pragma unroll
    for (int i = 0; i < 8; i++) {
        m[i] = -INFINITY; l[i] = 0.f;
        #pragma unroll
        for (int j = 0; j < 4; j++) oacc[i][j] = 0.f;
    }

    const int ntiles = 2 * qblk + 2;
    for (int t = 0; t < ntiles; t++) {
        const int k0 = t * FA_BK;

        {
            int j     = tid >> 2;
            int dbase = (tid & 3) * 16;
            const float* kp = Kh + (size_t)(k0 + j) * HD + dbase;
            const float* vp = Vh + (size_t)(k0 + j) * HD + dbase;
            #pragma unroll
            for (int d = 0; d < 16; d += 4) {
                float4 kv = *(const float4*)(kp + d);
                Ks[(dbase + d + 0) * 64 + j] = kv.x;
                Ks[(dbase + d + 1) * 64 + j] = kv.y;
                Ks[(dbase + d + 2) * 64 + j] = kv.z;
                Ks[(dbase + d + 3) * 64 + j] = kv.w;
                *(float4*)(Vs + j * 64 + dbase + d) = *(const float4*)(vp + d);
            }
        }
        __syncthreads();

        float sacc[8][4];
        #pragma unroll
        for (int i = 0; i < 8; i++)
            #pragma unroll
            for (int j = 0; j < 4; j++) sacc[i][j] = 0.f;

        #pragma unroll 8
        for (int kk = 0; kk < 64; kk++) {
            float4 qa = *(const float4*)(Qs + kk * 128 + tr * 8);
            float4 qb = *(const float4*)(Qs + kk * 128 + tr * 8 + 4);
            float4 kr = *(const float4*)(Ks + kk * 64 + tc * 4);
            float qr[8] = {qa.x, qa.y, qa.z, qa.w, qb.x, qb.y, qb.z, qb.w};
            float kc[4] = {kr.x, kr.y, kr.z, kr.w};
            #pragma unroll
            for (int i = 0; i < 8; i++)
                #pragma unroll
                for (int j = 0; j < 4; j++)
                    sacc[i][j] = fmaf(qr[i], kc[j], sacc[i][j]);
        }

        const bool need_mask = (k0 + FA_BK - 1 > q0);
        #pragma unroll
        for (int i = 0; i < 8; i++) {
            int grow = q0 + tr * 8 + i;
            #pragma unroll
            for (int j = 0; j < 4; j++) {
                float s = sacc[i][j] * ATT_SCALE;
                if (need_mask && (k0 + tc * 4 + j > grow)) s = -INFINITY;
                sacc[i][j] = s;
            }
        }

        #pragma unroll
        for (int i = 0; i < 8; i++) {
            float rmax = fmaxf(fmaxf(sacc[i][0], sacc[i][1]),
                               fmaxf(sacc[i][2], sacc[i][3]));
            rmax = fmaxf(rmax, __shfl_xor_sync(0xffffffffu, rmax, 1));
            rmax = fmaxf(rmax, __shfl_xor_sync(0xffffffffu, rmax, 2));
            rmax = fmaxf(rmax, __shfl_xor_sync(0xffffffffu, rmax, 4));
            rmax = fmaxf(rmax, __shfl_xor_sync(0xffffffffu, rmax, 8));

            float mnew = fmaxf(m[i], rmax);
            float resc = __expf(m[i] - mnew);
            m[i] = mnew;

            float p0 = __expf(sacc[i][0] - mnew);
            float p1 = __expf(sacc[i][1] - mnew);
            float p2 = __expf(sacc[i][2] - mnew);
            float p3 = __expf(sacc[i][3] - mnew);
            float psum = (p0 + p1) + (p2 + p3);
            psum += __shfl_xor_sync(0xffffffffu, psum, 1);
            psum += __shfl_xor_sync(0xffffffffu, psum, 2);
            psum += __shfl_xor_sync(0xffffffffu, psum, 4);
            psum += __shfl_xor_sync(0xffffffffu, psum, 8);

            l[i] = l[i] * resc + psum;
            #pragma unroll
            for (int j = 0; j < 4; j++) oacc[i][j] *= resc;

            float4 pv = make_float4(p0, p1, p2, p3);
            *(float4*)(Ps + (tr * 8 + i) * PSS + tc * 4) = pv;
        }
        __syncthreads();

        #pragma unroll 2
        for (int j4 = 0; j4 < 64; j4 += 4) {
            float4 v0 = *(const float4*)(Vs + (j4 + 0) * 64 + tc * 4);
            float4 v1 = *(const float4*)(Vs + (j4 + 1) * 64 + tc * 4);
            float4 v2 = *(const float4*)(Vs + (j4 + 2) * 64 + tc * 4);
            float4 v3 = *(const float4*)(Vs + (j4 + 3) * 64 + tc * 4);
            #pragma unroll
            for (int i = 0; i < 8; i++) {
                float4 p = *(const float4*)(Ps + (tr * 8 + i) * PSS + j4);
                oacc[i][0] = fmaf(p.x, v0.x, oacc[i][0]);
                oacc[i][1] = fmaf(p.x, v0.y, oacc[i][1]);
                oacc[i][2] = fmaf(p.x, v0.z, oacc[i][2]);
                oacc[i][3] = fmaf(p.x, v0.w, oacc[i][3]);
                oacc[i][0] = fmaf(p.y, v1.x, oacc[i][0]);
                oacc[i][1] = fmaf(p.y, v1.y, oacc[i][1]);
                oacc[i][2] = fmaf(p.y, v1.z, oacc[i][2]);
                oacc[i][3] = fmaf(p.y, v1.w, oacc[i][3]);
                oacc[i][0] = fmaf(p.z, v2.x, oacc[i][0]);
                oacc[i][1] = fmaf(p.z, v2.y, oacc[i][1]);
                oacc[i][2] = fmaf(p.z, v2.z, oacc[i][2]);
                oacc[i][3] = fmaf(p.z, v2.w, oacc[i][3]);
                oacc[i][0] = fmaf(p.w, v3.x, oacc[i][0]);
                oacc[i][1] = fmaf(p.w, v3.y, oacc[i][1]);
                oacc[i][2] = fmaf(p.w, v3.z, oacc[i][2]);
                oacc[i][3] = fmaf(p.w, v3.w, oacc[i][3]);
            }
        }
        __syncthreads();
    }

    const int b = bh >> 4, h = bh & 15;
    #pragma unroll
    for (int i = 0; i < 8; i++) {
        float inv = 1.0f / l[i];
        int grow = q0 + tr * 8 + i;
        float* op = g_o + ((size_t)(b * TSEQ) + grow) * DIM + h * HD + tc * 4;
        float4 v;
        v.x = oacc[i][0] * inv;
        v.y = oacc[i][1] * inv;
        v.z = oacc[i][2] * inv;
        v.w = oacc[i][3] * inv;
        *(float4*)op = v;
    }
}

// ---------------------------------------------------------------------------
extern "C" void kernel_launch(void* const* d_in, const int* in_sizes, int n_in,
                              void* d_out, int out_size)
{
    const float* x      = (const float*)d_in[0];
    const float* w_qkv  = (const float*)d_in[1];
    const float* w_proj = (const float*)d_in[2];
    const float* b_proj = (const float*)d_in[3];
    float* out = (float*)d_out;

    float* o_p = nullptr;
    cudaGetSymbolAddress((void**)&o_p, g_o);
    u32 *xh, *xl, *oh, *ol, *wqh, *wql, *wph, *wpl;
    cudaGetSymbolAddress((void**)&xh,  g_xh);
    cudaGetSymbolAddress((void**)&xl,  g_xl);
    cudaGetSymbolAddress((void**)&oh,  g_oh);
    cudaGetSymbolAddress((void**)&ol,  g_ol);
    cudaGetSymbolAddress((void**)&wqh, g_wqh);
    cudaGetSymbolAddress((void**)&wql, g_wql);
    cudaGetSymbolAddress((void**)&wph, g_wph);
    cudaGetSymbolAddress((void**)&wpl, g_wpl);

    cudaFuncSetAttribute(mma_gemm2,
                         cudaFuncAttributeMaxDynamicSharedMemorySize, G2_SMEM);

    // 0) prepass: split/transpose operands to bf16 hi/lo
    const int xpairs = TOKENS * DIM / 2;
    split_rows<<<(xpairs + 255) / 256, 256>>>(x, xh, xl, xpairs);
    transpose_split<<<dim3(QKV_N / 32, DIM / 64), 256>>>(w_qkv, wqh, wql, QKV_N, DIM);
    transpose_split<<<dim3(DIM / 32, DIM / 64), 256>>>(w_proj, wph, wpl, DIM, DIM);

    // 1) qkv = x @ w_qkv, scattered into g_q/g_k/g_v
    mma_gemm2<<<dim3(QKV_N / 128, TOKENS / 128), 256, G2_SMEM>>>(
        xh, xl, wqh, wql, nullptr, nullptr, QKV_N, DIM, 1);

    // 2) rope in-place on q, k
    int nwarps = BHEADS * TSEQ;
    rope_inplace<<<(nwarps * 32 + 255) / 256, 256>>>();

    // 3) flash attention (fp32)
    size_t fa_smem_bytes = FA_SMEM_FLOATS * sizeof(float);
    cudaFuncSetAttribute(flash_attn2,
                         cudaFuncAttributeMaxDynamicSharedMemorySize,
                         (int)fa_smem_bytes);
    flash_attn2<<<dim3(TSEQ / FA_BQ, BHEADS), 256, fa_smem_bytes>>>();

    // 4) split g_o, then out = g_o @ w_proj + b_proj
    split_rows<<<(xpairs + 255) / 256, 256>>>(o_p, oh, ol, xpairs);
    mma_gemm2<<<dim3(DIM / 128, TOKENS / 128), 256, G2_SMEM>>>(
        oh, ol, wph, wpl, out, b_proj, DIM, DIM, 0);
}

// round 7
// speedup vs baseline: 2.0753x; 2.0753x over previous
#include <cuda_runtime.h>
#include <cuda_bf16.h>
#include <stdint.h>
#include <math.h>

typedef unsigned int u32;

#define TOKENS 4096
#define DIM    1024
#define QKV_N  3072
#define NH     16
#define HD     64
#define TSEQ   2048
#define BHEADS 32
// 0.125 * log2(e)
#define SCALE2 0.18033688011112042f

// ---------------- global scratch ----------------
__device__ float g_q[BHEADS * TSEQ * HD];   // [bh][t][d] (pre-rope fp32)
__device__ float g_k[BHEADS * TSEQ * HD];
__device__ float g_v[BHEADS * TSEQ * HD];
__device__ float g_o[TOKENS * DIM];         // token-major

__device__ float2 g_trig[TSEQ * 32];        // (sin, cos) per (t, rot-index)

// pre-split bf16 hi/lo, pairs along d: [bh][t][32] u32
__device__ u32 g_qh[BHEADS * TSEQ * 32], g_ql[BHEADS * TSEQ * 32];
__device__ u32 g_kh[BHEADS * TSEQ * 32], g_kl[BHEADS * TSEQ * 32];
// V transposed, pairs along t: [bh][d][1024] u32
__device__ u32 g_vth[BHEADS * HD * (TSEQ / 2)], g_vtl[BHEADS * HD * (TSEQ / 2)];

// ---------------- helpers ----------------
__device__ __forceinline__ void mma_bf16(float c[4],
                                         const u32 a[4], const u32 b[2])
{
    asm volatile(
        "mma.sync.aligned.m16n8k16.row.col.f32.bf16.bf16.f32 "
        "{%0,%1,%2,%3}, {%4,%5,%6,%7}, {%8,%9}, {%0,%1,%2,%3};"
        : "+f"(c[0]), "+f"(c[1]), "+f"(c[2]), "+f"(c[3])
        : "r"(a[0]), "r"(a[1]), "r"(a[2]), "r"(a[3]),
          "r"(b[0]), "r"(b[1]));
}

__device__ __forceinline__ void split_pack(float x0, float x1,
                                           u32& hi, u32& lo)
{
    __nv_bfloat162 H = __floats2bfloat162_rn(x0, x1);
    float2 hf = __bfloat1622float2(H);
    __nv_bfloat162 L = __floats2bfloat162_rn(x0 - hf.x, x1 - hf.y);
    hi = *(u32*)&H;
    lo = *(u32*)&L;
}

// FFMA-only exp2 (no MUFU): magic-add round + degree-5 poly + exponent insert.
__device__ __forceinline__ float exp2_fast(float x)
{
    x = fmaxf(x, -60.0f);
    float t  = __fadd_rn(x, 12582912.0f);          // 1.5 * 2^23
    int   n  = __float_as_int(t) << 23;
    float ni = __fadd_rn(t, -12582912.0f);
    float r  = __fadd_rn(x, -ni);                  // r in [-0.5, 0.5]
    float p  = 1.3333558e-3f;
    p = fmaf(p, r, 9.6181291e-3f);
    p = fmaf(p, r, 5.5504109e-2f);
    p = fmaf(p, r, 2.4022651e-1f);
    p = fmaf(p, r, 6.9314718e-1f);
    p = fmaf(p, r, 1.0f);
    return __int_as_float(__float_as_int(p) + n);
}

// ---------------------------------------------------------------------------
// bf16x3 split-GEMM on tensor cores (R5 kernel, known-good).
// ---------------------------------------------------------------------------
__global__ __launch_bounds__(256)
void mma_gemm(const float* __restrict__ A, const float* __restrict__ B,
              float* __restrict__ C, const float* __restrict__ bias,
              int N, int K, int epi)
{
    __shared__ u32 Ah[16][132], Al[16][132];
    __shared__ u32 Bh[16][132], Bl[16][132];

    const int tid  = threadIdx.x;
    const int wid  = tid >> 5;
    const int lane = tid & 31;
    const int r8   = lane >> 2;
    const int c4   = lane & 3;
    const int wm   = (wid >> 2) * 64;
    const int wn   = (wid & 3) * 32;
    const int brow = blockIdx.y, bcol = blockIdx.x;

    const int a_row = tid & 127;
    const int a_ks  = (tid >> 7) * 16;
    const float* Ap = A + (size_t)(brow * 128 + a_row) * K + a_ks;

    const int b_n  = tid & 127;
    const int b_kh = (tid >> 7) * 8;
    const float* Bp = B + bcol * 128 + b_n;

    float acc[4][4][4];
    #pragma unroll
    for (int i = 0; i < 4; i++)
        #pragma unroll
        for (int j = 0; j < 4; j++)
            #pragma unroll
            for (int r = 0; r < 4; r++) acc[i][j][r] = 0.f;

    float aL[16], bL[16];

    #pragma unroll
    for (int q = 0; q < 4; q++)
        *(float4*)&aL[q * 4] = *(const float4*)(Ap + q * 4);
    #pragma unroll
    for (int i = 0; i < 8; i++) {
        int gk = 2 * (b_kh + i);
        bL[2 * i]     = Bp[(size_t)gk * N];
        bL[2 * i + 1] = Bp[(size_t)(gk + 1) * N];
    }

    for (int k0 = 0; k0 < K; k0 += 32) {
        #pragma unroll
        for (int j = 0; j < 8; j++) {
            u32 hi, lo;
            split_pack(aL[2 * j], aL[2 * j + 1], hi, lo);
            Ah[(a_ks >> 1) + j][a_row] = hi;
            Al[(a_ks >> 1) + j][a_row] = lo;
        }
        #pragma unroll
        for (int i = 0; i < 8; i++) {
            u32 hi, lo;
            split_pack(bL[2 * i], bL[2 * i + 1], hi, lo);
            Bh[b_kh + i][b_n] = hi;
            Bl[b_kh + i][b_n] = lo;
        }
        __syncthreads();

        if (k0 + 32 < K) {
            #pragma unroll
            for (int q = 0; q < 4; q++)
                *(float4*)&aL[q * 4] = *(const float4*)(Ap + k0 + 32 + q * 4);
            #pragma unroll
            for (int i = 0; i < 8; i++) {
                int gk = k0 + 32 + 2 * (b_kh + i);
                bL[2 * i]     = Bp[(size_t)gk * N];
                bL[2 * i + 1] = Bp[(size_t)(gk + 1) * N];
            }
        }

        #pragma unroll
        for (int kk = 0; kk < 16; kk += 8) {
            u32 ah[4][4], al[4][4], bh[4][2], bl[4][2];
            #pragma unroll
            for (int mf = 0; mf < 4; mf++) {
                int m = wm + mf * 16 + r8;
                ah[mf][0] = Ah[kk + c4][m];
                ah[mf][1] = Ah[kk + c4][m + 8];
                ah[mf][2] = Ah[kk + 4 + c4][m];
                ah[mf][3] = Ah[kk + 4 + c4][m + 8];
                al[mf][0] = Al[kk + c4][m];
                al[mf][1] = Al[kk + c4][m + 8];
                al[mf][2] = Al[kk + 4 + c4][m];
                al[mf][3] = Al[kk + 4 + c4][m + 8];
            }
            #pragma unroll
            for (int nf = 0; nf < 4; nf++) {
                int n = wn + nf * 8 + r8;
                bh[nf][0] = Bh[kk + c4][n];
                bh[nf][1] = Bh[kk + 4 + c4][n];
                bl[nf][0] = Bl[kk + c4][n];
                bl[nf][1] = Bl[kk + 4 + c4][n];
            }
            #pragma unroll
            for (int mf = 0; mf < 4; mf++)
                #pragma unroll
                for (int nf = 0; nf < 4; nf++)
                    mma_bf16(acc[mf][nf], ah[mf], bh[nf]);
            #pragma unroll
            for (int mf = 0; mf < 4; mf++)
                #pragma unroll
                for (int nf = 0; nf < 4; nf++)
                    mma_bf16(acc[mf][nf], ah[mf], bl[nf]);
            #pragma unroll
            for (int mf = 0; mf < 4; mf++)
                #pragma unroll
                for (int nf = 0; nf < 4; nf++)
                    mma_bf16(acc[mf][nf], al[mf], bh[nf]);
        }
        __syncthreads();
    }

    if (!epi) {
        #pragma unroll
        for (int nf = 0; nf < 4; nf++) {
            const int cg = bcol * 128 + wn + nf * 8 + c4 * 2;
            float bx = bias ? bias[cg]     : 0.f;
            float by = bias ? bias[cg + 1] : 0.f;
            #pragma unroll
            for (int mf = 0; mf < 4; mf++) {
                const int rg = brow * 128 + wm + mf * 16 + r8;
                float2 v0 = make_float2(acc[mf][nf][0] + bx, acc[mf][nf][1] + by);
                float2 v1 = make_float2(acc[mf][nf][2] + bx, acc[mf][nf][3] + by);
                *(float2*)(C + (size_t)rg * N + cg)       = v0;
                *(float2*)(C + (size_t)(rg + 8) * N + cg) = v1;
            }
        }
    } else {
        #pragma unroll
        for (int nf = 0; nf < 4; nf++) {
            const int n_g   = bcol * 128 + wn + nf * 8 + c4 * 2;
            const int which = n_g >> 10;
            const int rmod  = n_g & 1023;
            const int h     = rmod >> 6;
            const int d     = rmod & 63;
            float* base = (which == 0) ? g_q : (which == 1) ? g_k : g_v;
            #pragma unroll
            for (int mf = 0; mf < 4; mf++) {
                const int m_g0 = brow * 128 + wm + mf * 16 + r8;
                #pragma unroll
                for (int half = 0; half < 2; half++) {
                    const int m_g = m_g0 + half * 8;
                    const int b   = m_g >> 11;
                    const int t   = m_g & 2047;
                    float2 v = make_float2(acc[mf][nf][half * 2],
                                           acc[mf][nf][half * 2 + 1]);
                    *(float2*)(base + (((size_t)(b * 16 + h) * TSEQ + t) * HD + d)) = v;
                }
            }
        }
    }
}

// ---------------------------------------------------------------------------
// trig table: sin/cos per (t, rotation index)
// ---------------------------------------------------------------------------
__global__ __launch_bounds__(256)
void trig_table()
{
    int idx = blockIdx.x * 256 + threadIdx.x;
    if (idx >= TSEQ * 32) return;
    int t = idx >> 5, i = idx & 31;
    float freq = expf(-9.210340371976184f * (float)i * (1.0f / 32.0f));
    float ang = (float)t * freq;
    float s, c;
    sincosf(ang, &s, &c);
    g_trig[idx] = make_float2(s, c);
}

// ---------------------------------------------------------------------------
// RoPE + split Q,K to bf16 hi/lo pairs along d. Q pre-scaled by SCALE2.
// One warp per (bh, t).
// ---------------------------------------------------------------------------
__global__ __launch_bounds__(256)
void rope_split()
{
    int gw   = (blockIdx.x * 256 + threadIdx.x) >> 5;
    int lane = threadIdx.x & 31;
    if (gw >= BHEADS * TSEQ) return;
    int bh = gw >> 11;
    int t  = gw & 2047;

    float2 sc = g_trig[t * 32 + lane];
    float s = sc.x, c = sc.y;

    size_t off = ((size_t)bh * TSEQ + t) * HD;

    float q1 = g_q[off + lane], q2 = g_q[off + lane + 32];
    float qa = (q1 * c - q2 * s) * SCALE2;
    float qb = (q1 * s + q2 * c) * SCALE2;

    float k1 = g_k[off + lane], k2 = g_k[off + lane + 32];
    float ka = k1 * c - k2 * s;
    float kb = k1 * s + k2 * c;

    int src = (2 * lane) & 31;
    float qa0 = __shfl_sync(0xffffffffu, qa, src);
    float qa1 = __shfl_sync(0xffffffffu, qa, src + 1);
    float qb0 = __shfl_sync(0xffffffffu, qb, src);
    float qb1 = __shfl_sync(0xffffffffu, qb, src + 1);
    float ka0 = __shfl_sync(0xffffffffu, ka, src);
    float ka1 = __shfl_sync(0xffffffffu, ka, src + 1);
    float kb0 = __shfl_sync(0xffffffffu, kb, src);
    float kb1 = __shfl_sync(0xffffffffu, kb, src + 1);

    float e0 = (lane < 16) ? qa0 : qb0;
    float e1 = (lane < 16) ? qa1 : qb1;
    u32 hi, lo;
    split_pack(e0, e1, hi, lo);
    size_t po = ((size_t)bh * TSEQ + t) * 32 + lane;
    g_qh[po] = hi;
    g_ql[po] = lo;

    e0 = (lane < 16) ? ka0 : kb0;
    e1 = (lane < 16) ? ka1 : kb1;
    split_pack(e0, e1, hi, lo);
    g_kh[po] = hi;
    g_kl[po] = lo;
}

// ---------------------------------------------------------------------------
// V transpose + split: g_v [bh][t][64] -> g_vth/g_vtl [bh][d][t2] pairs along t
// Block handles (bh, 64-token tile). 256 threads.
// ---------------------------------------------------------------------------
__global__ __launch_bounds__(256)
void v_transpose()
{
    __shared__ float sv[64][65];
    const int bh = blockIdx.y, tb = blockIdx.x;
    const int tid = threadIdx.x;

    {
        int r = tid >> 2, cb = (tid & 3) * 16;
        const float* vp = g_v + ((size_t)bh * TSEQ + tb * 64 + r) * HD + cb;
        #pragma unroll
        for (int i = 0; i < 16; i += 4) {
            float4 v = *(const float4*)(vp + i);
            sv[r][cb + i + 0] = v.x;
            sv[r][cb + i + 1] = v.y;
            sv[r][cb + i + 2] = v.z;
            sv[r][cb + i + 3] = v.w;
        }
    }
    __syncthreads();

    int t2 = tid & 31, dbase = (tid >> 5) * 8;
    #pragma unroll
    for (int i = 0; i < 8; i++) {
        int d = dbase + i;
        u32 hi, lo;
        split_pack(sv[2 * t2][d], sv[2 * t2 + 1][d], hi, lo);
        size_t o = ((size_t)bh * HD + d) * (TSEQ / 2) + tb * 32 + t2;
        g_vth[o] = hi;
        g_vtl[o] = lo;
    }
}

// ---------------------------------------------------------------------------
// Flash attention on tensor cores (bf16x3 S, bf16x3 PV), exp2-domain softmax.
// BQ=128 (8 warps x 16 rows), BK=64. 256 threads.
// ---------------------------------------------------------------------------
#define FKS 36   // smem row stride (conflict-free frag reads)

__global__ __launch_bounds__(256)
void flash_mma()
{
    __shared__ u32 Ksh[64 * FKS], Ksl[64 * FKS];
    __shared__ u32 Vsh[64 * FKS], Vsl[64 * FKS];

    const int bh   = blockIdx.y;
    const int qblk = gridDim.x - 1 - blockIdx.x;   // heavy blocks first
    const int q0   = qblk * 128;

    const int tid  = threadIdx.x;
    const int w    = tid >> 5;
    const int lane = tid & 31;
    const int r8   = lane >> 2;
    const int c4   = lane & 3;

    // Q fragments (persist whole kernel)
    u32 qh[4][4], ql[4][4];
    {
        const u32* Qh = g_qh + ((size_t)bh * TSEQ + q0 + w * 16) * 32;
        const u32* Ql = g_ql + ((size_t)bh * TSEQ + q0 + w * 16) * 32;
        #pragma unroll
        for (int g = 0; g < 4; g++) {
            qh[g][0] = Qh[(size_t)r8 * 32 + 8 * g + c4];
            qh[g][1] = Qh[(size_t)(r8 + 8) * 32 + 8 * g + c4];
            qh[g][2] = Qh[(size_t)r8 * 32 + 8 * g + c4 + 4];
            qh[g][3] = Qh[(size_t)(r8 + 8) * 32 + 8 * g + c4 + 4];
            ql[g][0] = Ql[(size_t)r8 * 32 + 8 * g + c4];
            ql[g][1] = Ql[(size_t)(r8 + 8) * 32 + 8 * g + c4];
            ql[g][2] = Ql[(size_t)r8 * 32 + 8 * g + c4 + 4];
            ql[g][3] = Ql[(size_t)(r8 + 8) * 32 + 8 * g + c4 + 4];
        }
    }

    float oacc[8][4];
    #pragma unroll
    for (int i = 0; i < 8; i++)
        #pragma unroll
        for (int j = 0; j < 4; j++) oacc[i][j] = 0.f;
    float m0 = -1e30f, m1 = -1e30f, l0 = 0.f, l1 = 0.f;

    const int row0 = q0 + w * 16 + r8;
    const int row1 = row0 + 8;

    const u32* Kgh = g_kh + (size_t)bh * TSEQ * 32;
    const u32* Kgl = g_kl + (size_t)bh * TSEQ * 32;
    const u32* Vgh = g_vth + (size_t)bh * HD * (TSEQ / 2);
    const u32* Vgl = g_vtl + (size_t)bh * HD * (TSEQ / 2);

    const int ntiles = 2 * qblk + 2;
    for (int tile = 0; tile < ntiles; tile++) {
        const int k0 = tile * 64;

        // load K and V^T tiles (hi/lo) into smem
        {
            int r = tid >> 2, cb = (tid & 3) * 8;
            const u32* kh = Kgh + (size_t)(k0 + r) * 32 + cb;
            const u32* kl = Kgl + (size_t)(k0 + r) * 32 + cb;
            const u32* vh = Vgh + (size_t)r * (TSEQ / 2) + (k0 >> 1) + cb;
            const u32* vl = Vgl + (size_t)r * (TSEQ / 2) + (k0 >> 1) + cb;
            u32* dk_h = Ksh + r * FKS + cb;
            u32* dk_l = Ksl + r * FKS + cb;
            u32* dv_h = Vsh + r * FKS + cb;
            u32* dv_l = Vsl + r * FKS + cb;
            *(uint4*)(dk_h)     = *(const uint4*)(kh);
            *(uint4*)(dk_h + 4) = *(const uint4*)(kh + 4);
            *(uint4*)(dk_l)     = *(const uint4*)(kl);
            *(uint4*)(dk_l + 4) = *(const uint4*)(kl + 4);
            *(uint4*)(dv_h)     = *(const uint4*)(vh);
            *(uint4*)(dv_h + 4) = *(const uint4*)(vh + 4);
            *(uint4*)(dv_l)     = *(const uint4*)(vl);
            *(uint4*)(dv_l + 4) = *(const uint4*)(vl + 4);
        }
        __syncthreads();

        const bool active = (k0 <= q0 + w * 16 + 15);
        if (active) {
            // ---- S = Q K^T (bf16x3) ----
            float sacc[8][4];
            #pragma unroll
            for (int i = 0; i < 8; i++)
                #pragma unroll
                for (int j = 0; j < 4; j++) sacc[i][j] = 0.f;

            #pragma unroll
            for (int g = 0; g < 4; g++) {
                #pragma unroll
                for (int nf = 0; nf < 8; nf++) {
                    const int base = (nf * 8 + r8) * FKS + 8 * g + c4;
                    u32 bhx[2], blx[2];
                    bhx[0] = Ksh[base]; bhx[1] = Ksh[base + 4];
                    blx[0] = Ksl[base]; blx[1] = Ksl[base + 4];
                    mma_bf16(sacc[nf], qh[g], bhx);
                    mma_bf16(sacc[nf], qh[g], blx);
                    mma_bf16(sacc[nf], ql[g], bhx);
                }
            }

            // ---- causal mask (last tiles only) ----
            if (k0 + 63 > row0) {
                #pragma unroll
                for (int nf = 0; nf < 8; nf++) {
                    const int n0 = k0 + nf * 8 + 2 * c4;
                    if (n0 > row0)     sacc[nf][0] = -1e30f;
                    if (n0 + 1 > row0) sacc[nf][1] = -1e30f;
                    if (n0 > row1)     sacc[nf][2] = -1e30f;
                    if (n0 + 1 > row1) sacc[nf][3] = -1e30f;
                }
            }

            // ---- online softmax (exp2 domain) ----
            float rm0 = -1e30f, rm1 = -1e30f;
            #pragma unroll
            for (int nf = 0; nf < 8; nf++) {
                rm0 = fmaxf(rm0, fmaxf(sacc[nf][0], sacc[nf][1]));
                rm1 = fmaxf(rm1, fmaxf(sacc[nf][2], sacc[nf][3]));
            }
            rm0 = fmaxf(rm0, __shfl_xor_sync(0xffffffffu, rm0, 1));
            rm0 = fmaxf(rm0, __shfl_xor_sync(0xffffffffu, rm0, 2));
            rm1 = fmaxf(rm1, __shfl_xor_sync(0xffffffffu, rm1, 1));
            rm1 = fmaxf(rm1, __shfl_xor_sync(0xffffffffu, rm1, 2));

            const float mn0 = fmaxf(m0, rm0);
            const float mn1 = fmaxf(m1, rm1);
            const float rs0 = exp2_fast(m0 - mn0);
            const float rs1 = exp2_fast(m1 - mn1);
            m0 = mn0; m1 = mn1;

            float sum0 = 0.f, sum1 = 0.f;
            #pragma unroll
            for (int nf = 0; nf < 8; nf++) {
                sacc[nf][0] = exp2_fast(sacc[nf][0] - mn0);
                sacc[nf][1] = exp2_fast(sacc[nf][1] - mn0);
                sacc[nf][2] = exp2_fast(sacc[nf][2] - mn1);
                sacc[nf][3] = exp2_fast(sacc[nf][3] - mn1);
                sum0 += sacc[nf][0] + sacc[nf][1];
                sum1 += sacc[nf][2] + sacc[nf][3];
            }
            sum0 += __shfl_xor_sync(0xffffffffu, sum0, 1);
            sum0 += __shfl_xor_sync(0xffffffffu, sum0, 2);
            sum1 += __shfl_xor_sync(0xffffffffu, sum1, 1);
            sum1 += __shfl_xor_sync(0xffffffffu, sum1, 2);
            l0 = l0 * rs0 + sum0;
            l1 = l1 * rs1 + sum1;

            #pragma unroll
            for (int nf = 0; nf < 8; nf++) {
                oacc[nf][0] *= rs0;
                oacc[nf][1] *= rs0;
                oacc[nf][2] *= rs1;
                oacc[nf][3] *= rs1;
            }

            // ---- O += P V (bf16x3); P frags are repacked sacc ----
            #pragma unroll
            for (int g = 0; g < 4; g++) {
                u32 ph[4], pl[4];
                split_pack(sacc[2 * g][0],     sacc[2 * g][1],     ph[0], pl[0]);
                split_pack(sacc[2 * g][2],     sacc[2 * g][3],     ph[1], pl[1]);
                split_pack(sacc[2 * g + 1][0], sacc[2 * g + 1][1], ph[2], pl[2]);
                split_pack(sacc[2 * g + 1][2], sacc[2 * g + 1][3], ph[3], pl[3]);
                #pragma unroll
                for (int nf = 0; nf < 8; nf++) {
                    const int base = (nf * 8 + r8) * FKS + 8 * g + c4;
                    u32 bhx[2], blx[2];
                    bhx[0] = Vsh[base]; bhx[1] = Vsh[base + 4];
                    blx[0] = Vsl[base]; blx[1] = Vsl[base + 4];
                    mma_bf16(oacc[nf], ph, bhx);
                    mma_bf16(oacc[nf], ph, blx);
                    mma_bf16(oacc[nf], pl, bhx);
                }
            }
        }
        __syncthreads();
    }

    // ---- epilogue ----
    const float inv0 = 1.0f / l0;
    const float inv1 = 1.0f / l1;
    const int b = bh >> 4, h = bh & 15;
    #pragma unroll
    for (int nf = 0; nf < 8; nf++) {
        const int d = nf * 8 + 2 * c4;
        float2 v0 = make_float2(oacc[nf][0] * inv0, oacc[nf][1] * inv0);
        float2 v1 = make_float2(oacc[nf][2] * inv1, oacc[nf][3] * inv1);
        *(float2*)(g_o + ((size_t)(b * TSEQ) + row0) * DIM + h * HD + d) = v0;
        *(float2*)(g_o + ((size_t)(b * TSEQ) + row1) * DIM + h * HD + d) = v1;
    }
}

// ---------------------------------------------------------------------------
extern "C" void kernel_launch(void* const* d_in, const int* in_sizes, int n_in,
                              void* d_out, int out_size)
{
    const float* x      = (const float*)d_in[0];
    const float* w_qkv  = (const float*)d_in[1];
    const float* w_proj = (const float*)d_in[2];
    const float* b_proj = (const float*)d_in[3];
    float* out = (float*)d_out;

    float* o_p = nullptr;
    cudaGetSymbolAddress((void**)&o_p, g_o);

    // 0) trig table
    trig_table<<<(TSEQ * 32 + 255) / 256, 256>>>();

    // 1) qkv = x @ w_qkv -> g_q/g_k/g_v (tensor cores, bf16x3)
    mma_gemm<<<dim3(QKV_N / 128, TOKENS / 128), 256>>>(
        x, w_qkv, nullptr, nullptr, QKV_N, DIM, 1);

    // 2) rope + hi/lo split of Q (pre-scaled), K
    rope_split<<<(BHEADS * TSEQ * 32 + 255) / 256, 256>>>();

    // 3) V transpose + split
    v_transpose<<<dim3(TSEQ / 64, BHEADS), 256>>>();

    // 4) flash attention on tensor cores
    flash_mma<<<dim3(TSEQ / 128, BHEADS), 256>>>();

    // 5) out = g_o @ w_proj + b_proj (tensor cores, bf16x3)
    mma_gemm<<<dim3(DIM / 128, TOKENS / 128), 256>>>(
        o_p, w_proj, out, b_proj, DIM, DIM, 0);
}

// round 8
// speedup vs baseline: 2.4680x; 1.1892x over previous
#include <cuda_runtime.h>
#include <cuda_bf16.h>
#include <stdint.h>
#include <math.h>

typedef unsigned int u32;

#define TOKENS 4096
#define DIM    1024
#define QKV_N  3072
#define NH     16
#define HD     64
#define TSEQ   2048
#define BHEADS 32
// 0.125 * log2(e)
#define SCALE2 0.18033688011112042f

// ---------------- global scratch ----------------
__device__ float g_q[BHEADS * TSEQ * HD];   // [bh][t][d] (pre-rope fp32)
__device__ float g_k[BHEADS * TSEQ * HD];
__device__ float g_v[BHEADS * TSEQ * HD];
__device__ float g_o[TOKENS * DIM];         // token-major

__device__ float2 g_trig[TSEQ * 32];

// GEMM operands, bf16 hi/lo pair-packed along K
__device__ u32 g_xh[TOKENS * DIM / 2],  g_xl[TOKENS * DIM / 2];   // [M][K2]
__device__ u32 g_oh2[TOKENS * DIM / 2], g_ol2[TOKENS * DIM / 2];  // [M][K2]
__device__ u32 g_wqh[DIM / 2 * QKV_N],  g_wql[DIM / 2 * QKV_N];   // [K2][N]
__device__ u32 g_wph[DIM / 2 * DIM],    g_wpl[DIM / 2 * DIM];     // [K2][N]

// attention operands (flash) — pre-split bf16 hi/lo
__device__ u32 g_qh[BHEADS * TSEQ * 32], g_ql[BHEADS * TSEQ * 32];
__device__ u32 g_kh[BHEADS * TSEQ * 32], g_kl[BHEADS * TSEQ * 32];
__device__ u32 g_vth[BHEADS * HD * (TSEQ / 2)], g_vtl[BHEADS * HD * (TSEQ / 2)];

// ---------------- helpers ----------------
__device__ __forceinline__ void mma_bf16(float c[4],
                                         const u32 a[4], const u32 b[2])
{
    asm volatile(
        "mma.sync.aligned.m16n8k16.row.col.f32.bf16.bf16.f32 "
        "{%0,%1,%2,%3}, {%4,%5,%6,%7}, {%8,%9}, {%0,%1,%2,%3};"
        : "+f"(c[0]), "+f"(c[1]), "+f"(c[2]), "+f"(c[3])
        : "r"(a[0]), "r"(a[1]), "r"(a[2]), "r"(a[3]),
          "r"(b[0]), "r"(b[1]));
}

__device__ __forceinline__ void split_pack(float x0, float x1,
                                           u32& hi, u32& lo)
{
    __nv_bfloat162 H = __floats2bfloat162_rn(x0, x1);
    float2 hf = __bfloat1622float2(H);
    __nv_bfloat162 L = __floats2bfloat162_rn(x0 - hf.x, x1 - hf.y);
    hi = *(u32*)&H;
    lo = *(u32*)&L;
}

// FFMA-only exp2 (no MUFU)
__device__ __forceinline__ float exp2_fast(float x)
{
    x = fmaxf(x, -60.0f);
    float t  = __fadd_rn(x, 12582912.0f);
    int   n  = __float_as_int(t) << 23;
    float ni = __fadd_rn(t, -12582912.0f);
    float r  = __fadd_rn(x, -ni);
    float p  = 1.3333558e-3f;
    p = fmaf(p, r, 9.6181291e-3f);
    p = fmaf(p, r, 5.5504109e-2f);
    p = fmaf(p, r, 2.4022651e-1f);
    p = fmaf(p, r, 6.9314718e-1f);
    p = fmaf(p, r, 1.0f);
    return __int_as_float(__float_as_int(p) + n);
}

__device__ __forceinline__ void cp16(u32* smem_dst, const u32* gsrc)
{
    unsigned d = (unsigned)__cvta_generic_to_shared(smem_dst);
    asm volatile("cp.async.cg.shared.global [%0], [%1], 16;" :: "r"(d), "l"(gsrc));
}

// ---------------- prepass kernels ----------------
// A-side: [M][K] fp32 -> [M][K2] u32 hi/lo (pairs along K). Fully linear.
__global__ __launch_bounds__(256)
void split_pairs_rows(const float* __restrict__ src, u32* __restrict__ hi,
                      u32* __restrict__ lo, int npairs)
{
    int i = blockIdx.x * 256 + threadIdx.x;
    if (i >= npairs) return;
    float2 v = ((const float2*)src)[i];
    split_pack(v.x, v.y, hi[i], lo[i]);
}

// B-side: [K][N] fp32 -> [K2][N] u32 hi/lo, pair = (B[2k2][n], B[2k2+1][n])
__global__ __launch_bounds__(256)
void split_pairs_cols(const float* __restrict__ B, u32* __restrict__ hi,
                      u32* __restrict__ lo, int N, int K)
{
    int i = blockIdx.x * 256 + threadIdx.x;
    int K2 = K >> 1;
    if (i >= K2 * N) return;
    int k2 = i / N, n = i - k2 * N;
    float v0 = B[(size_t)(2 * k2) * N + n];
    float v1 = B[(size_t)(2 * k2 + 1) * N + n];
    split_pack(v0, v1, hi[i], lo[i]);
}

// ---------------------------------------------------------------------------
// mma_gemm3: bf16x3 GEMM, pre-split operands, cp.async 2-stage, 2 CTAs/SM.
// A: [M][K2] hi/lo. B: [K2][N] hi/lo. Tile 128x128, BK=32 (16 pairs).
// 256 threads, 8 warps of 64x32. epi=0: C=A@B+bias. epi=1: qkv scatter.
// ---------------------------------------------------------------------------
#define A_ST  (128 * 20)        // u32 per A array per stage
#define B_ST  (16 * 136)        // u32 per B array per stage
#define G3_SMEM ((2 * 2 * A_ST + 2 * 2 * B_ST) * 4)  // 75776 bytes

__global__ __launch_bounds__(256, 2)
void mma_gemm3(const u32* __restrict__ Agh, const u32* __restrict__ Agl,
               const u32* __restrict__ Bgh, const u32* __restrict__ Bgl,
               float* __restrict__ C, const float* __restrict__ bias,
               int N, int K, int epi)
{
    extern __shared__ u32 sm3[];
    u32* AsH = sm3;                       // [2][128][20]
    u32* AsL = AsH + 2 * A_ST;
    u32* BsH = AsL + 2 * A_ST;            // [2][16][136]
    u32* BsL = BsH + 2 * B_ST;

    const int tid  = threadIdx.x;
    const int wid  = tid >> 5;
    const int lane = tid & 31;
    const int r8   = lane >> 2;
    const int c4   = lane & 3;
    const int wm   = (wid >> 2) * 64;
    const int wn   = (wid & 3) * 32;
    const int brow = blockIdx.y, bcol = blockIdx.x;
    const int K2   = K >> 1;

    // A copy map: row ar (0..127), col chunk acb (0 or 8)
    const int ar  = tid & 127;
    const int acb = (tid >> 7) * 8;
    const u32* Aph = Agh + (size_t)(brow * 128 + ar) * K2 + acb;
    const u32* Apl = Agl + (size_t)(brow * 128 + ar) * K2 + acb;
    // B copy map: k2-row bk (0..15), col chunk bnc (8 u32)
    const int bk  = tid >> 4;
    const int bnc = (tid & 15) * 8;
    const u32* Bph = Bgh + (size_t)bk * N + bcol * 128 + bnc;
    const u32* Bpl = Bgl + (size_t)bk * N + bcol * 128 + bnc;

    float acc[4][4][4];
    #pragma unroll
    for (int i = 0; i < 4; i++)
        #pragma unroll
        for (int j = 0; j < 4; j++)
            #pragma unroll
            for (int r = 0; r < 4; r++) acc[i][j][r] = 0.f;

    auto issue = [&](int k2base, int s) {
        u32* aH = AsH + s * A_ST + ar * 20 + acb;
        u32* aL = AsL + s * A_ST + ar * 20 + acb;
        cp16(aH,     Aph + k2base);
        cp16(aH + 4, Aph + k2base + 4);
        cp16(aL,     Apl + k2base);
        cp16(aL + 4, Apl + k2base + 4);
        u32* bH = BsH + s * B_ST + bk * 136 + bnc;
        u32* bL = BsL + s * B_ST + bk * 136 + bnc;
        cp16(bH,     Bph + (size_t)k2base * N);
        cp16(bH + 4, Bph + (size_t)k2base * N + 4);
        cp16(bL,     Bpl + (size_t)k2base * N);
        cp16(bL + 4, Bpl + (size_t)k2base * N + 4);
        asm volatile("cp.async.commit_group;");
    };

    issue(0, 0);
    issue(16, 1);

    const int nst = K2 >> 4;   // stages of 16 pairs (BK=32)
    for (int ks = 0; ks < nst; ks++) {
        asm volatile("cp.async.wait_group 1;");
        __syncthreads();
        const int s = ks & 1;
        const u32* aH = AsH + s * A_ST;
        const u32* aL = AsL + s * A_ST;
        const u32* bH = BsH + s * B_ST;
        const u32* bL = BsL + s * B_ST;

        #pragma unroll
        for (int kk = 0; kk < 2; kk++) {
            const int kc = kk * 8 + c4;
            u32 bh[4][2], bl[4][2];
            #pragma unroll
            for (int nf = 0; nf < 4; nf++) {
                const int n = wn + nf * 8 + r8;
                bh[nf][0] = bH[kc * 136 + n];
                bh[nf][1] = bH[(kc + 4) * 136 + n];
                bl[nf][0] = bL[kc * 136 + n];
                bl[nf][1] = bL[(kc + 4) * 136 + n];
            }
            #pragma unroll
            for (int mf = 0; mf < 4; mf++) {
                const int m = wm + mf * 16 + r8;
                u32 ah[4], al[4];
                ah[0] = aH[m * 20 + kc];
                ah[1] = aH[(m + 8) * 20 + kc];
                ah[2] = aH[m * 20 + kc + 4];
                ah[3] = aH[(m + 8) * 20 + kc + 4];
                al[0] = aL[m * 20 + kc];
                al[1] = aL[(m + 8) * 20 + kc];
                al[2] = aL[m * 20 + kc + 4];
                al[3] = aL[(m + 8) * 20 + kc + 4];
                #pragma unroll
                for (int nf = 0; nf < 4; nf++) {
                    mma_bf16(acc[mf][nf], ah, bh[nf]);
                    mma_bf16(acc[mf][nf], ah, bl[nf]);
                    mma_bf16(acc[mf][nf], al, bh[nf]);
                }
            }
        }
        __syncthreads();
        if (ks + 2 < nst) issue((ks + 2) * 16, s);
        else asm volatile("cp.async.commit_group;");
    }

    if (!epi) {
        #pragma unroll
        for (int nf = 0; nf < 4; nf++) {
            const int cg = bcol * 128 + wn + nf * 8 + c4 * 2;
            float bx = bias ? bias[cg]     : 0.f;
            float by = bias ? bias[cg + 1] : 0.f;
            #pragma unroll
            for (int mf = 0; mf < 4; mf++) {
                const int rg = brow * 128 + wm + mf * 16 + r8;
                float2 v0 = make_float2(acc[mf][nf][0] + bx, acc[mf][nf][1] + by);
                float2 v1 = make_float2(acc[mf][nf][2] + bx, acc[mf][nf][3] + by);
                *(float2*)(C + (size_t)rg * N + cg)       = v0;
                *(float2*)(C + (size_t)(rg + 8) * N + cg) = v1;
            }
        }
    } else {
        #pragma unroll
        for (int nf = 0; nf < 4; nf++) {
            const int n_g   = bcol * 128 + wn + nf * 8 + c4 * 2;
            const int which = n_g >> 10;
            const int rmod  = n_g & 1023;
            const int h     = rmod >> 6;
            const int d     = rmod & 63;
            float* base = (which == 0) ? g_q : (which == 1) ? g_k : g_v;
            #pragma unroll
            for (int mf = 0; mf < 4; mf++) {
                const int m_g0 = brow * 128 + wm + mf * 16 + r8;
                #pragma unroll
                for (int half = 0; half < 2; half++) {
                    const int m_g = m_g0 + half * 8;
                    const int b   = m_g >> 11;
                    const int t   = m_g & 2047;
                    float2 v = make_float2(acc[mf][nf][half * 2],
                                           acc[mf][nf][half * 2 + 1]);
                    *(float2*)(base + (((size_t)(b * 16 + h) * TSEQ + t) * HD + d)) = v;
                }
            }
        }
    }
}

// ---------------------------------------------------------------------------
__global__ __launch_bounds__(256)
void trig_table()
{
    int idx = blockIdx.x * 256 + threadIdx.x;
    if (idx >= TSEQ * 32) return;
    int t = idx >> 5, i = idx & 31;
    float freq = expf(-9.210340371976184f * (float)i * (1.0f / 32.0f));
    float ang = (float)t * freq;
    float s, c;
    sincosf(ang, &s, &c);
    g_trig[idx] = make_float2(s, c);
}

// ---------------------------------------------------------------------------
// RoPE + split Q,K to bf16 hi/lo pairs along d. Q pre-scaled by SCALE2.
// ---------------------------------------------------------------------------
__global__ __launch_bounds__(256)
void rope_split()
{
    int gw   = (blockIdx.x * 256 + threadIdx.x) >> 5;
    int lane = threadIdx.x & 31;
    if (gw >= BHEADS * TSEQ) return;
    int bh = gw >> 11;
    int t  = gw & 2047;

    float2 sc = g_trig[t * 32 + lane];
    float s = sc.x, c = sc.y;

    size_t off = ((size_t)bh * TSEQ + t) * HD;

    float q1 = g_q[off + lane], q2 = g_q[off + lane + 32];
    float qa = (q1 * c - q2 * s) * SCALE2;
    float qb = (q1 * s + q2 * c) * SCALE2;

    float k1 = g_k[off + lane], k2 = g_k[off + lane + 32];
    float ka = k1 * c - k2 * s;
    float kb = k1 * s + k2 * c;

    int src = (2 * lane) & 31;
    float qa0 = __shfl_sync(0xffffffffu, qa, src);
    float qa1 = __shfl_sync(0xffffffffu, qa, src + 1);
    float qb0 = __shfl_sync(0xffffffffu, qb, src);
    float qb1 = __shfl_sync(0xffffffffu, qb, src + 1);
    float ka0 = __shfl_sync(0xffffffffu, ka, src);
    float ka1 = __shfl_sync(0xffffffffu, ka, src + 1);
    float kb0 = __shfl_sync(0xffffffffu, kb, src);
    float kb1 = __shfl_sync(0xffffffffu, kb, src + 1);

    float e0 = (lane < 16) ? qa0 : qb0;
    float e1 = (lane < 16) ? qa1 : qb1;
    u32 hi, lo;
    split_pack(e0, e1, hi, lo);
    size_t po = ((size_t)bh * TSEQ + t) * 32 + lane;
    g_qh[po] = hi;
    g_ql[po] = lo;

    e0 = (lane < 16) ? ka0 : kb0;
    e1 = (lane < 16) ? ka1 : kb1;
    split_pack(e0, e1, hi, lo);
    g_kh[po] = hi;
    g_kl[po] = lo;
}

// ---------------------------------------------------------------------------
__global__ __launch_bounds__(256)
void v_transpose()
{
    __shared__ float sv[64][65];
    const int bh = blockIdx.y, tb = blockIdx.x;
    const int tid = threadIdx.x;

    {
        int r = tid >> 2, cb = (tid & 3) * 16;
        const float* vp = g_v + ((size_t)bh * TSEQ + tb * 64 + r) * HD + cb;
        #pragma unroll
        for (int i = 0; i < 16; i += 4) {
            float4 v = *(const float4*)(vp + i);
            sv[r][cb + i + 0] = v.x;
            sv[r][cb + i + 1] = v.y;
            sv[r][cb + i + 2] = v.z;
            sv[r][cb + i + 3] = v.w;
        }
    }
    __syncthreads();

    int t2 = tid & 31, dbase = (tid >> 5) * 8;
    #pragma unroll
    for (int i = 0; i < 8; i++) {
        int d = dbase + i;
        u32 hi, lo;
        split_pack(sv[2 * t2][d], sv[2 * t2 + 1][d], hi, lo);
        size_t o = ((size_t)bh * HD + d) * (TSEQ / 2) + tb * 32 + t2;
        g_vth[o] = hi;
        g_vtl[o] = lo;
    }
}

// ---------------------------------------------------------------------------
// Flash attention on tensor cores (bf16x3), exp2-domain softmax.
// ---------------------------------------------------------------------------
#define FKS 36

__global__ __launch_bounds__(256)
void flash_mma()
{
    __shared__ u32 Ksh[64 * FKS], Ksl[64 * FKS];
    __shared__ u32 Vsh[64 * FKS], Vsl[64 * FKS];

    const int bh   = blockIdx.y;
    const int qblk = gridDim.x - 1 - blockIdx.x;
    const int q0   = qblk * 128;

    const int tid  = threadIdx.x;
    const int w    = tid >> 5;
    const int lane = tid & 31;
    const int r8   = lane >> 2;
    const int c4   = lane & 3;

    u32 qh[4][4], ql[4][4];
    {
        const u32* Qh = g_qh + ((size_t)bh * TSEQ + q0 + w * 16) * 32;
        const u32* Ql = g_ql + ((size_t)bh * TSEQ + q0 + w * 16) * 32;
        #pragma unroll
        for (int g = 0; g < 4; g++) {
            qh[g][0] = Qh[(size_t)r8 * 32 + 8 * g + c4];
            qh[g][1] = Qh[(size_t)(r8 + 8) * 32 + 8 * g + c4];
            qh[g][2] = Qh[(size_t)r8 * 32 + 8 * g + c4 + 4];
            qh[g][3] = Qh[(size_t)(r8 + 8) * 32 + 8 * g + c4 + 4];
            ql[g][0] = Ql[(size_t)r8 * 32 + 8 * g + c4];
            ql[g][1] = Ql[(size_t)(r8 + 8) * 32 + 8 * g + c4];
            ql[g][2] = Ql[(size_t)r8 * 32 + 8 * g + c4 + 4];
            ql[g][3] = Ql[(size_t)(r8 + 8) * 32 + 8 * g + c4 + 4];
        }
    }

    float oacc[8][4];
    #pragma unroll
    for (int i = 0; i < 8; i++)
        #pragma unroll
        for (int j = 0; j < 4; j++) oacc[i][j] = 0.f;
    float m0 = -1e30f, m1 = -1e30f, l0 = 0.f, l1 = 0.f;

    const int row0 = q0 + w * 16 + r8;
    const int row1 = row0 + 8;

    const u32* Kgh = g_kh + (size_t)bh * TSEQ * 32;
    const u32* Kgl = g_kl + (size_t)bh * TSEQ * 32;
    const u32* Vgh = g_vth + (size_t)bh * HD * (TSEQ / 2);
    const u32* Vgl = g_vtl + (size_t)bh * HD * (TSEQ / 2);

    const int ntiles = 2 * qblk + 2;
    for (int tile = 0; tile < ntiles; tile++) {
        const int k0 = tile * 64;

        {
            int r = tid >> 2, cb = (tid & 3) * 8;
            const u32* kh = Kgh + (size_t)(k0 + r) * 32 + cb;
            const u32* kl = Kgl + (size_t)(k0 + r) * 32 + cb;
            const u32* vh = Vgh + (size_t)r * (TSEQ / 2) + (k0 >> 1) + cb;
            const u32* vl = Vgl + (size_t)r * (TSEQ / 2) + (k0 >> 1) + cb;
            u32* dk_h = Ksh + r * FKS + cb;
            u32* dk_l = Ksl + r * FKS + cb;
            u32* dv_h = Vsh + r * FKS + cb;
            u32* dv_l = Vsl + r * FKS + cb;
            *(uint4*)(dk_h)     = *(const uint4*)(kh);
            *(uint4*)(dk_h + 4) = *(const uint4*)(kh + 4);
            *(uint4*)(dk_l)     = *(const uint4*)(kl);
            *(uint4*)(dk_l + 4) = *(const uint4*)(kl + 4);
            *(uint4*)(dv_h)     = *(const uint4*)(vh);
            *(uint4*)(dv_h + 4) = *(const uint4*)(vh + 4);
            *(uint4*)(dv_l)     = *(const uint4*)(vl);
            *(uint4*)(dv_l + 4) = *(const uint4*)(vl + 4);
        }
        __syncthreads();

        const bool active = (k0 <= q0 + w * 16 + 15);
        if (active) {
            float sacc[8][4];
            #pragma unroll
            for (int i = 0; i < 8; i++)
                #pragma unroll
                for (int j = 0; j < 4; j++) sacc[i][j] = 0.f;

            #pragma unroll
            for (int g = 0; g < 4; g++) {
                #pragma unroll
                for (int nf = 0; nf < 8; nf++) {
                    const int base = (nf * 8 + r8) * FKS + 8 * g + c4;
                    u32 bhx[2], blx[2];
                    bhx[0] = Ksh[base]; bhx[1] = Ksh[base + 4];
                    blx[0] = Ksl[base]; blx[1] = Ksl[base + 4];
                    mma_bf16(sacc[nf], qh[g], bhx);
                    mma_bf16(sacc[nf], qh[g], blx);
                    mma_bf16(sacc[nf], ql[g], bhx);
                }
            }

            if (k0 + 63 > row0) {
                #pragma unroll
                for (int nf = 0; nf < 8; nf++) {
                    const int n0 = k0 + nf * 8 + 2 * c4;
                    if (n0 > row0)     sacc[nf][0] = -1e30f;
                    if (n0 + 1 > row0) sacc[nf][1] = -1e30f;
                    if (n0 > row1)     sacc[nf][2] = -1e30f;
                    if (n0 + 1 > row1) sacc[nf][3] = -1e30f;
                }
            }

            float rm0 = -1e30f, rm1 = -1e30f;
            #pragma unroll
            for (int nf = 0; nf < 8; nf++) {
                rm0 = fmaxf(rm0, fmaxf(sacc[nf][0], sacc[nf][1]));
                rm1 = fmaxf(rm1, fmaxf(sacc[nf][2], sacc[nf][3]));
            }
            rm0 = fmaxf(rm0, __shfl_xor_sync(0xffffffffu, rm0, 1));
            rm0 = fmaxf(rm0, __shfl_xor_sync(0xffffffffu, rm0, 2));
            rm1 = fmaxf(rm1, __shfl_xor_sync(0xffffffffu, rm1, 1));
            rm1 = fmaxf(rm1, __shfl_xor_sync(0xffffffffu, rm1, 2));

            const float mn0 = fmaxf(m0, rm0);
            const float mn1 = fmaxf(m1, rm1);
            const float rs0 = exp2_fast(m0 - mn0);
            const float rs1 = exp2_fast(m1 - mn1);
            m0 = mn0; m1 = mn1;

            float sum0 = 0.f, sum1 = 0.f;
            #pragma unroll
            for (int nf = 0; nf < 8; nf++) {
                sacc[nf][0] = exp2_fast(sacc[nf][0] - mn0);
                sacc[nf][1] = exp2_fast(sacc[nf][1] - mn0);
                sacc[nf][2] = exp2_fast(sacc[nf][2] - mn1);
                sacc[nf][3] = exp2_fast(sacc[nf][3] - mn1);
                sum0 += sacc[nf][0] + sacc[nf][1];
                sum1 += sacc[nf][2] + sacc[nf][3];
            }
            sum0 += __shfl_xor_sync(0xffffffffu, sum0, 1);
            sum0 += __shfl_xor_sync(0xffffffffu, sum0, 2);
            sum1 += __shfl_xor_sync(0xffffffffu, sum1, 1);
            sum1 += __shfl_xor_sync(0xffffffffu, sum1, 2);
            l0 = l0 * rs0 + sum0;
            l1 = l1 * rs1 + sum1;

            #pragma unroll
            for (int nf = 0; nf < 8; nf++) {
                oacc[nf][0] *= rs0;
                oacc[nf][1] *= rs0;
                oacc[nf][2] *= rs1;
                oacc[nf][3] *= rs1;
            }

            #pragma unroll
            for (int g = 0; g < 4; g++) {
                u32 ph[4], pl[4];
                split_pack(sacc[2 * g][0],     sacc[2 * g][1],     ph[0], pl[0]);
                split_pack(sacc[2 * g][2],     sacc[2 * g][3],     ph[1], pl[1]);
                split_pack(sacc[2 * g + 1][0], sacc[2 * g + 1][1], ph[2], pl[2]);
                split_pack(sacc[2 * g + 1][2], sacc[2 * g + 1][3], ph[3], pl[3]);
                #pragma unroll
                for (int nf = 0; nf < 8; nf++) {
                    const int base = (nf * 8 + r8) * FKS + 8 * g + c4;
                    u32 bhx[2], blx[2];
                    bhx[0] = Vsh[base]; bhx[1] = Vsh[base + 4];
                    blx[0] = Vsl[base]; blx[1] = Vsl[base + 4];
                    mma_bf16(oacc[nf], ph, bhx);
                    mma_bf16(oacc[nf], ph, blx);
                    mma_bf16(oacc[nf], pl, bhx);
                }
            }
        }
        __syncthreads();
    }

    const float inv0 = 1.0f / l0;
    const float inv1 = 1.0f / l1;
    const int b = bh >> 4, h = bh & 15;
    #pragma unroll
    for (int nf = 0; nf < 8; nf++) {
        const int d = nf * 8 + 2 * c4;
        float2 v0 = make_float2(oacc[nf][0] * inv0, oacc[nf][1] * inv0);
        float2 v1 = make_float2(oacc[nf][2] * inv1, oacc[nf][3] * inv1);
        *(float2*)(g_o + ((size_t)(b * TSEQ) + row0) * DIM + h * HD + d) = v0;
        *(float2*)(g_o + ((size_t)(b * TSEQ) + row1) * DIM + h * HD + d) = v1;
    }
}

// ---------------------------------------------------------------------------
extern "C" void kernel_launch(void* const* d_in, const int* in_sizes, int n_in,
                              void* d_out, int out_size)
{
    const float* x      = (const float*)d_in[0];
    const float* w_qkv  = (const float*)d_in[1];
    const float* w_proj = (const float*)d_in[2];
    const float* b_proj = (const float*)d_in[3];
    float* out = (float*)d_out;

    float* o_p = nullptr;
    cudaGetSymbolAddress((void**)&o_p, g_o);
    u32 *xh, *xl, *oh, *ol, *wqh, *wql, *wph, *wpl;
    cudaGetSymbolAddress((void**)&xh,  g_xh);
    cudaGetSymbolAddress((void**)&xl,  g_xl);
    cudaGetSymbolAddress((void**)&oh,  g_oh2);
    cudaGetSymbolAddress((void**)&ol,  g_ol2);
    cudaGetSymbolAddress((void**)&wqh, g_wqh);
    cudaGetSymbolAddress((void**)&wql, g_wql);
    cudaGetSymbolAddress((void**)&wph, g_wph);
    cudaGetSymbolAddress((void**)&wpl, g_wpl);

    cudaFuncSetAttribute(mma_gemm3,
                         cudaFuncAttributeMaxDynamicSharedMemorySize, G3_SMEM);

    // 0) trig table + operand splits
    trig_table<<<(TSEQ * 32 + 255) / 256, 256>>>();
    const int xpairs = TOKENS * DIM / 2;
    split_pairs_rows<<<(xpairs + 255) / 256, 256>>>(x, xh, xl, xpairs);
    split_pairs_cols<<<((DIM / 2) * QKV_N + 255) / 256, 256>>>(w_qkv, wqh, wql, QKV_N, DIM);
    split_pairs_cols<<<((DIM / 2) * DIM + 255) / 256, 256>>>(w_proj, wph, wpl, DIM, DIM);

    // 1) qkv = x @ w_qkv -> g_q/g_k/g_v
    mma_gemm3<<<dim3(QKV_N / 128, TOKENS / 128), 256, G3_SMEM>>>(
        xh, xl, wqh, wql, nullptr, nullptr, QKV_N, DIM, 1);

    // 2) rope + split
    rope_split<<<(BHEADS * TSEQ * 32 + 255) / 256, 256>>>();

    // 3) V transpose + split
    v_transpose<<<dim3(TSEQ / 64, BHEADS), 256>>>();

    // 4) flash attention (tensor cores)
    flash_mma<<<dim3(TSEQ / 128, BHEADS), 256>>>();

    // 5) out = g_o @ w_proj + b_proj
    split_pairs_rows<<<(xpairs + 255) / 256, 256>>>(o_p, oh, ol, xpairs);
    mma_gemm3<<<dim3(DIM / 128, TOKENS / 128), 256, G3_SMEM>>>(
        oh, ol, wph, wpl, out, b_proj, DIM, DIM, 0);
}

// round 10
// speedup vs baseline: 3.2592x; 1.3206x over previous
#include <cuda_runtime.h>
#include <cuda_fp16.h>
#include <stdint.h>
#include <math.h>

typedef unsigned int u32;

#define TOKENS 4096
#define DIM    1024
#define QKV_N  3072
#define NH     16
#define HD     64
#define TSEQ   2048
#define BHEADS 32
// 0.125 * log2(e)
#define SCALE2 0.18033688011112042f

// ---------------- global scratch ----------------
__device__ float g_q[BHEADS * TSEQ * HD];   // [bh][t][d] (pre-rope fp32)
__device__ float g_k[BHEADS * TSEQ * HD];
__device__ float g_v[BHEADS * TSEQ * HD];
__device__ float g_o[TOKENS * DIM];         // token-major

__device__ float2 g_trig[TSEQ * 32];

// GEMM A operands: [M][K2] u32 (fp16 pairs along K), hi+lo split
__device__ u32 g_xh[TOKENS * DIM / 2],  g_xl[TOKENS * DIM / 2];
__device__ u32 g_oh2[TOKENS * DIM / 2], g_ol2[TOKENS * DIM / 2];
// GEMM B operands: [K2][N] u32 (fp16 pairs along K), rounded single
__device__ u32 g_wqh[DIM / 2 * QKV_N];
__device__ u32 g_wph[DIM / 2 * DIM];

// flash operands: Q split hi/lo, K/V rounded single (fp16 pairs)
__device__ u32 g_qh[BHEADS * TSEQ * 32], g_ql[BHEADS * TSEQ * 32];
__device__ u32 g_kh[BHEADS * TSEQ * 32];
__device__ u32 g_vth[BHEADS * HD * (TSEQ / 2)];

// ---------------- helpers ----------------
__device__ __forceinline__ void mma_f16(float c[4],
                                        const u32 a[4], const u32 b[2])
{
    asm volatile(
        "mma.sync.aligned.m16n8k16.row.col.f32.f16.f16.f32 "
        "{%0,%1,%2,%3}, {%4,%5,%6,%7}, {%8,%9}, {%0,%1,%2,%3};"
        : "+f"(c[0]), "+f"(c[1]), "+f"(c[2]), "+f"(c[3])
        : "r"(a[0]), "r"(a[1]), "r"(a[2]), "r"(a[3]),
          "r"(b[0]), "r"(b[1]));
}

__device__ __forceinline__ void split_pack_f16(float x0, float x1,
                                               u32& hi, u32& lo)
{
    __half2 H = __floats2half2_rn(x0, x1);
    float2 hf = __half22float2(H);
    __half2 L = __floats2half2_rn(x0 - hf.x, x1 - hf.y);
    hi = *(u32*)&H;
    lo = *(u32*)&L;
}

__device__ __forceinline__ u32 pack_f16(float x0, float x1)
{
    __half2 H = __floats2half2_rn(x0, x1);
    return *(u32*)&H;
}

// FFMA-only exp2 (no MUFU)
__device__ __forceinline__ float exp2_fast(float x)
{
    x = fmaxf(x, -60.0f);
    float t  = __fadd_rn(x, 12582912.0f);
    int   n  = __float_as_int(t) << 23;
    float ni = __fadd_rn(t, -12582912.0f);
    float r  = __fadd_rn(x, -ni);
    float p  = 1.3333558e-3f;
    p = fmaf(p, r, 9.6181291e-3f);
    p = fmaf(p, r, 5.5504109e-2f);
    p = fmaf(p, r, 2.4022651e-1f);
    p = fmaf(p, r, 6.9314718e-1f);
    p = fmaf(p, r, 1.0f);
    return __int_as_float(__float_as_int(p) + n);
}

__device__ __forceinline__ void cp16(u32* smem_dst, const u32* gsrc)
{
    unsigned d = (unsigned)__cvta_generic_to_shared(smem_dst);
    asm volatile("cp.async.cg.shared.global [%0], [%1], 16;" :: "r"(d), "l"(gsrc));
}

// ---------------- prepass kernels ----------------
// A-side: [M][K] fp32 -> [M][K2] u32 fp16 hi/lo (pairs along K)
__global__ __launch_bounds__(256)
void split_pairs_rows(const float* __restrict__ src, u32* __restrict__ hi,
                      u32* __restrict__ lo, int npairs)
{
    int i = blockIdx.x * 256 + threadIdx.x;
    if (i >= npairs) return;
    float2 v = ((const float2*)src)[i];
    split_pack_f16(v.x, v.y, hi[i], lo[i]);
}

// B-side: [K][N] fp32 -> [K2][N] u32 fp16 (rounded, pairs along K)
__global__ __launch_bounds__(256)
void pack_pairs_cols(const float* __restrict__ B, u32* __restrict__ hi,
                     int N, int K)
{
    int i = blockIdx.x * 256 + threadIdx.x;
    int K2 = K >> 1;
    if (i >= K2 * N) return;
    int k2 = i / N, n = i - k2 * N;
    hi[i] = pack_f16(B[(size_t)(2 * k2) * N + n],
                     B[(size_t)(2 * k2 + 1) * N + n]);
}

// ---------------------------------------------------------------------------
// mma_gemm4: fp16 A-split 2-pass GEMM, cp.async 2-stage, 2 CTAs/SM.
// A: [M][K2] hi/lo. B: [K2][N] single. Tile 128x128, BK=32 (16 pairs).
// epi=0: C=A@B+bias. epi=1: qkv scatter into g_q/g_k/g_v.
// ---------------------------------------------------------------------------
#define A_ST  (128 * 20)        // u32 per A array per stage
#define B_ST  (16 * 136)        // u32 per B array per stage
#define G4_SMEM ((2 * 2 * A_ST + 2 * B_ST) * 4)  // 58368 bytes

__global__ __launch_bounds__(256, 2)
void mma_gemm4(const u32* __restrict__ Agh, const u32* __restrict__ Agl,
               const u32* __restrict__ Bgh,
               float* __restrict__ C, const float* __restrict__ bias,
               int N, int K, int epi)
{
    extern __shared__ u32 sm4[];
    u32* AsH = sm4;                       // [2][128][20]
    u32* AsL = AsH + 2 * A_ST;
    u32* BsH = AsL + 2 * A_ST;            // [2][16][136]

    const int tid  = threadIdx.x;
    const int wid  = tid >> 5;
    const int lane = tid & 31;
    const int r8   = lane >> 2;
    const int c4   = lane & 3;
    const int wm   = (wid >> 2) * 64;
    const int wn   = (wid & 3) * 32;
    const int brow = blockIdx.y, bcol = blockIdx.x;
    const int K2   = K >> 1;

    const int ar  = tid & 127;
    const int acb = (tid >> 7) * 8;
    const u32* Aph = Agh + (size_t)(brow * 128 + ar) * K2 + acb;
    const u32* Apl = Agl + (size_t)(brow * 128 + ar) * K2 + acb;
    const int bk  = tid >> 4;
    const int bnc = (tid & 15) * 8;
    const u32* Bph = Bgh + (size_t)bk * N + bcol * 128 + bnc;

    float acc[4][4][4];
    #pragma unroll
    for (int i = 0; i < 4; i++)
        #pragma unroll
        for (int j = 0; j < 4; j++)
            #pragma unroll
            for (int r = 0; r < 4; r++) acc[i][j][r] = 0.f;

    auto issue = [&](int k2base, int s) {
        u32* aH = AsH + s * A_ST + ar * 20 + acb;
        u32* aL = AsL + s * A_ST + ar * 20 + acb;
        cp16(aH,     Aph + k2base);
        cp16(aH + 4, Aph + k2base + 4);
        cp16(aL,     Apl + k2base);
        cp16(aL + 4, Apl + k2base + 4);
        u32* bH = BsH + s * B_ST + bk * 136 + bnc;
        cp16(bH,     Bph + (size_t)k2base * N);
        cp16(bH + 4, Bph + (size_t)k2base * N + 4);
        asm volatile("cp.async.commit_group;");
    };

    issue(0, 0);
    issue(16, 1);

    const int nst = K2 >> 4;   // stages of 16 pairs (BK=32)
    for (int ks = 0; ks < nst; ks++) {
        asm volatile("cp.async.wait_group 1;");
        __syncthreads();
        const int s = ks & 1;
        const u32* aH = AsH + s * A_ST;
        const u32* aL = AsL + s * A_ST;
        const u32* bH = BsH + s * B_ST;

        #pragma unroll
        for (int kk = 0; kk < 2; kk++) {
            const int kc = kk * 8 + c4;
            u32 bh[4][2];
            #pragma unroll
            for (int nf = 0; nf < 4; nf++) {
                const int n = wn + nf * 8 + r8;
                bh[nf][0] = bH[kc * 136 + n];
                bh[nf][1] = bH[(kc + 4) * 136 + n];
            }
            #pragma unroll
            for (int mf = 0; mf < 4; mf++) {
                const int m = wm + mf * 16 + r8;
                u32 ah[4], al[4];
                ah[0] = aH[m * 20 + kc];
                ah[1] = aH[(m + 8) * 20 + kc];
                ah[2] = aH[m * 20 + kc + 4];
                ah[3] = aH[(m + 8) * 20 + kc + 4];
                al[0] = aL[m * 20 + kc];
                al[1] = aL[(m + 8) * 20 + kc];
                al[2] = aL[m * 20 + kc + 4];
                al[3] = aL[(m + 8) * 20 + kc + 4];
                #pragma unroll
                for (int nf = 0; nf < 4; nf++) {
                    mma_f16(acc[mf][nf], ah, bh[nf]);
                    mma_f16(acc[mf][nf], al, bh[nf]);
                }
            }
        }
        __syncthreads();
        if (ks + 2 < nst) issue((ks + 2) * 16, s);
        else asm volatile("cp.async.commit_group;");
    }

    if (!epi) {
        #pragma unroll
        for (int nf = 0; nf < 4; nf++) {
            const int cg = bcol * 128 + wn + nf * 8 + c4 * 2;
            float bx = bias ? bias[cg]     : 0.f;
            float by = bias ? bias[cg + 1] : 0.f;
            #pragma unroll
            for (int mf = 0; mf < 4; mf++) {
                const int rg = brow * 128 + wm + mf * 16 + r8;
                float2 v0 = make_float2(acc[mf][nf][0] + bx, acc[mf][nf][1] + by);
                float2 v1 = make_float2(acc[mf][nf][2] + bx, acc[mf][nf][3] + by);
                *(float2*)(C + (size_t)rg * N + cg)       = v0;
                *(float2*)(C + (size_t)(rg + 8) * N + cg) = v1;
            }
        }
    } else {
        #pragma unroll
        for (int nf = 0; nf < 4; nf++) {
            const int n_g   = bcol * 128 + wn + nf * 8 + c4 * 2;
            const int which = n_g >> 10;
            const int rmod  = n_g & 1023;
            const int h     = rmod >> 6;
            const int d     = rmod & 63;
            float* base = (which == 0) ? g_q : (which == 1) ? g_k : g_v;
            #pragma unroll
            for (int mf = 0; mf < 4; mf++) {
                const int m_g0 = brow * 128 + wm + mf * 16 + r8;
                #pragma unroll
                for (int half = 0; half < 2; half++) {
                    const int m_g = m_g0 + half * 8;
                    const int b   = m_g >> 11;
                    const int t   = m_g & 2047;
                    float2 v = make_float2(acc[mf][nf][half * 2],
                                           acc[mf][nf][half * 2 + 1]);
                    *(float2*)(base + (((size_t)(b * 16 + h) * TSEQ + t) * HD + d)) = v;
                }
            }
        }
    }
}

// ---------------------------------------------------------------------------
__global__ __launch_bounds__(256)
void trig_table()
{
    int idx = blockIdx.x * 256 + threadIdx.x;
    if (idx >= TSEQ * 32) return;
    int t = idx >> 5, i = idx & 31;
    float freq = expf(-9.210340371976184f * (float)i * (1.0f / 32.0f));
    float ang = (float)t * freq;
    float s, c;
    sincosf(ang, &s, &c);
    g_trig[idx] = make_float2(s, c);
}

// ---------------------------------------------------------------------------
// RoPE + pack: Q split hi/lo (pre-scaled by SCALE2), K rounded single.
// ---------------------------------------------------------------------------
__global__ __launch_bounds__(256)
void rope_split()
{
    int gw   = (blockIdx.x * 256 + threadIdx.x) >> 5;
    int lane = threadIdx.x & 31;
    if (gw >= BHEADS * TSEQ) return;
    int bh = gw >> 11;
    int t  = gw & 2047;

    float2 sc = g_trig[t * 32 + lane];
    float s = sc.x, c = sc.y;

    size_t off = ((size_t)bh * TSEQ + t) * HD;

    float q1 = g_q[off + lane], q2 = g_q[off + lane + 32];
    float qa = (q1 * c - q2 * s) * SCALE2;
    float qb = (q1 * s + q2 * c) * SCALE2;

    float k1 = g_k[off + lane], k2 = g_k[off + lane + 32];
    float ka = k1 * c - k2 * s;
    float kb = k1 * s + k2 * c;

    int src = (2 * lane) & 31;
    float qa0 = __shfl_sync(0xffffffffu, qa, src);
    float qa1 = __shfl_sync(0xffffffffu, qa, src + 1);
    float qb0 = __shfl_sync(0xffffffffu, qb, src);
    float qb1 = __shfl_sync(0xffffffffu, qb, src + 1);
    float ka0 = __shfl_sync(0xffffffffu, ka, src);
    float ka1 = __shfl_sync(0xffffffffu, ka, src + 1);
    float kb0 = __shfl_sync(0xffffffffu, kb, src);
    float kb1 = __shfl_sync(0xffffffffu, kb, src + 1);

    float e0 = (lane < 16) ? qa0 : qb0;
    float e1 = (lane < 16) ? qa1 : qb1;
    u32 hi, lo;
    split_pack_f16(e0, e1, hi, lo);
    size_t po = ((size_t)bh * TSEQ + t) * 32 + lane;
    g_qh[po] = hi;
    g_ql[po] = lo;

    e0 = (lane < 16) ? ka0 : kb0;
    e1 = (lane < 16) ? ka1 : kb1;
    g_kh[po] = pack_f16(e0, e1);
}

// ---------------------------------------------------------------------------
__global__ __launch_bounds__(256)
void v_transpose()
{
    __shared__ float sv[64][65];
    const int bh = blockIdx.y, tb = blockIdx.x;
    const int tid = threadIdx.x;

    {
        int r = tid >> 2, cb = (tid & 3) * 16;
        const float* vp = g_v + ((size_t)bh * TSEQ + tb * 64 + r) * HD + cb;
        #pragma unroll
        for (int i = 0; i < 16; i += 4) {
            float4 v = *(const float4*)(vp + i);
            sv[r][cb + i + 0] = v.x;
            sv[r][cb + i + 1] = v.y;
            sv[r][cb + i + 2] = v.z;
            sv[r][cb + i + 3] = v.w;
        }
    }
    __syncthreads();

    int t2 = tid & 31, dbase = (tid >> 5) * 8;
    #pragma unroll
    for (int i = 0; i < 8; i++) {
        int d = dbase + i;
        size_t o = ((size_t)bh * HD + d) * (TSEQ / 2) + tb * 32 + t2;
        g_vth[o] = pack_f16(sv[2 * t2][d], sv[2 * t2 + 1][d]);
    }
}

// ---------------------------------------------------------------------------
// Flash attention: fp16 2-pass (Q/P split, K/V rounded), exp2 softmax.
// BQ=128 (8 warps x 16 rows), BK=64, 256 threads.
// ---------------------------------------------------------------------------
#define FKS 36

__global__ __launch_bounds__(256)
void flash_mma()
{
    __shared__ u32 Ksh[64 * FKS];
    __shared__ u32 Vsh[64 * FKS];

    const int bh   = blockIdx.y;
    const int qblk = gridDim.x - 1 - blockIdx.x;
    const int q0   = qblk * 128;

    const int tid  = threadIdx.x;
    const int w    = tid >> 5;
    const int lane = tid & 31;
    const int r8   = lane >> 2;
    const int c4   = lane & 3;

    u32 qh[4][4], ql[4][4];
    {
        const u32* Qh = g_qh + ((size_t)bh * TSEQ + q0 + w * 16) * 32;
        const u32* Ql = g_ql + ((size_t)bh * TSEQ + q0 + w * 16) * 32;
        #pragma unroll
        for (int g = 0; g < 4; g++) {
            qh[g][0] = Qh[(size_t)r8 * 32 + 8 * g + c4];
            qh[g][1] = Qh[(size_t)(r8 + 8) * 32 + 8 * g + c4];
            qh[g][2] = Qh[(size_t)r8 * 32 + 8 * g + c4 + 4];
            qh[g][3] = Qh[(size_t)(r8 + 8) * 32 + 8 * g + c4 + 4];
            ql[g][0] = Ql[(size_t)r8 * 32 + 8 * g + c4];
            ql[g][1] = Ql[(size_t)(r8 + 8) * 32 + 8 * g + c4];
            ql[g][2] = Ql[(size_t)r8 * 32 + 8 * g + c4 + 4];
            ql[g][3] = Ql[(size_t)(r8 + 8) * 32 + 8 * g + c4 + 4];
        }
    }

    float oacc[8][4];
    #pragma unroll
    for (int i = 0; i < 8; i++)
        #pragma unroll
        for (int j = 0; j < 4; j++) oacc[i][j] = 0.f;
    float m0 = -1e30f, m1 = -1e30f, l0 = 0.f, l1 = 0.f;

    const int row0 = q0 + w * 16 + r8;
    const int row1 = row0 + 8;

    const u32* Kgh = g_kh + (size_t)bh * TSEQ * 32;
    const u32* Vgh = g_vth + (size_t)bh * HD * (TSEQ / 2);

    const int ntiles = 2 * qblk + 2;
    for (int tile = 0; tile < ntiles; tile++) {
        const int k0 = tile * 64;

        {
            int r = tid >> 2, cb = (tid & 3) * 8;
            const u32* kh = Kgh + (size_t)(k0 + r) * 32 + cb;
            const u32* vh = Vgh + (size_t)r * (TSEQ / 2) + (k0 >> 1) + cb;
            u32* dk_h = Ksh + r * FKS + cb;
            u32* dv_h = Vsh + r * FKS + cb;
            *(uint4*)(dk_h)     = *(const uint4*)(kh);
            *(uint4*)(dk_h + 4) = *(const uint4*)(kh + 4);
            *(uint4*)(dv_h)     = *(const uint4*)(vh);
            *(uint4*)(dv_h + 4) = *(const uint4*)(vh + 4);
        }
        __syncthreads();

        const bool active = (k0 <= q0 + w * 16 + 15);
        if (active) {
            float sacc[8][4];
            #pragma unroll
            for (int i = 0; i < 8; i++)
                #pragma unroll
                for (int j = 0; j < 4; j++) sacc[i][j] = 0.f;

            #pragma unroll
            for (int g = 0; g < 4; g++) {
                #pragma unroll
                for (int nf = 0; nf < 8; nf++) {
                    const int base = (nf * 8 + r8) * FKS + 8 * g + c4;
                    u32 bhx[2];
                    bhx[0] = Ksh[base]; bhx[1] = Ksh[base + 4];
                    mma_f16(sacc[nf], qh[g], bhx);
                    mma_f16(sacc[nf], ql[g], bhx);
                }
            }

            if (k0 + 63 > row0) {
                #pragma unroll
                for (int nf = 0; nf < 8; nf++) {
                    const int n0 = k0 + nf * 8 + 2 * c4;
                    if (n0 > row0)     sacc[nf][0] = -1e30f;
                    if (n0 + 1 > row0) sacc[nf][1] = -1e30f;
                    if (n0 > row1)     sacc[nf][2] = -1e30f;
                    if (n0 + 1 > row1) sacc[nf][3] = -1e30f;
                }
            }

            float rm0 = -1e30f, rm1 = -1e30f;
            #pragma unroll
            for (int nf = 0; nf < 8; nf++) {
                rm0 = fmaxf(rm0, fmaxf(sacc[nf][0], sacc[nf][1]));
                rm1 = fmaxf(rm1, fmaxf(sacc[nf][2], sacc[nf][3]));
            }
            rm0 = fmaxf(rm0, __shfl_xor_sync(0xffffffffu, rm0, 1));
            rm0 = fmaxf(rm0, __shfl_xor_sync(0xffffffffu, rm0, 2));
            rm1 = fmaxf(rm1, __shfl_xor_sync(0xffffffffu, rm1, 1));
            rm1 = fmaxf(rm1, __shfl_xor_sync(0xffffffffu, rm1, 2));

            const float mn0 = fmaxf(m0, rm0);
            const float mn1 = fmaxf(m1, rm1);
            const float rs0 = exp2_fast(m0 - mn0);
            const float rs1 = exp2_fast(m1 - mn1);
            m0 = mn0; m1 = mn1;

            float sum0 = 0.f, sum1 = 0.f;
            #pragma unroll
            for (int nf = 0; nf < 8; nf++) {
                sacc[nf][0] = exp2_fast(sacc[nf][0] - mn0);
                sacc[nf][1] = exp2_fast(sacc[nf][1] - mn0);
                sacc[nf][2] = exp2_fast(sacc[nf][2] - mn1);
                sacc[nf][3] = exp2_fast(sacc[nf][3] - mn1);
                sum0 += sacc[nf][0] + sacc[nf][1];
                sum1 += sacc[nf][2] + sacc[nf][3];
            }
            sum0 += __shfl_xor_sync(0xffffffffu, sum0, 1);
            sum0 += __shfl_xor_sync(0xffffffffu, sum0, 2);
            sum1 += __shfl_xor_sync(0xffffffffu, sum1, 1);
            sum1 += __shfl_xor_sync(0xffffffffu, sum1, 2);
            l0 = l0 * rs0 + sum0;
            l1 = l1 * rs1 + sum1;

            #pragma unroll
            for (int nf = 0; nf < 8; nf++) {
                oacc[nf][0] *= rs0;
                oacc[nf][1] *= rs0;
                oacc[nf][2] *= rs1;
                oacc[nf][3] *= rs1;
            }

            #pragma unroll
            for (int g = 0; g < 4; g++) {
                u32 ph[4], pl[4];
                split_pack_f16(sacc[2 * g][0],     sacc[2 * g][1],     ph[0], pl[0]);
                split_pack_f16(sacc[2 * g][2],     sacc[2 * g][3],     ph[1], pl[1]);
                split_pack_f16(sacc[2 * g + 1][0], sacc[2 * g + 1][1], ph[2], pl[2]);
                split_pack_f16(sacc[2 * g + 1][2], sacc[2 * g + 1][3], ph[3], pl[3]);
                #pragma unroll
                for (int nf = 0; nf < 8; nf++) {
                    const int base = (nf * 8 + r8) * FKS + 8 * g + c4;
                    u32 bhx[2];
                    bhx[0] = Vsh[base]; bhx[1] = Vsh[base + 4];
                    mma_f16(oacc[nf], ph, bhx);
                    mma_f16(oacc[nf], pl, bhx);
                }
            }
        }
        __syncthreads();
    }

    const float inv0 = 1.0f / l0;
    const float inv1 = 1.0f / l1;
    const int b = bh >> 4, h = bh & 15;
    #pragma unroll
    for (int nf = 0; nf < 8; nf++) {
        const int d = nf * 8 + 2 * c4;
        float2 v0 = make_float2(oacc[nf][0] * inv0, oacc[nf][1] * inv0);
        float2 v1 = make_float2(oacc[nf][2] * inv1, oacc[nf][3] * inv1);
        *(float2*)(g_o + ((size_t)(b * TSEQ) + row0) * DIM + h * HD + d) = v0;
        *(float2*)(g_o + ((size_t)(b * TSEQ) + row1) * DIM + h * HD + d) = v1;
    }
}

// ---------------------------------------------------------------------------
extern "C" void kernel_launch(void* const* d_in, const int* in_sizes, int n_in,
                              void* d_out, int out_size)
{
    const float* x      = (const float*)d_in[0];
    const float* w_qkv  = (const float*)d_in[1];
    const float* w_proj = (const float*)d_in[2];
    const float* b_proj = (const float*)d_in[3];
    float* out = (float*)d_out;

    float* o_p = nullptr;
    cudaGetSymbolAddress((void**)&o_p, g_o);
    u32 *xh, *xl, *oh, *ol, *wqh, *wph;
    cudaGetSymbolAddress((void**)&xh,  g_xh);
    cudaGetSymbolAddress((void**)&xl,  g_xl);
    cudaGetSymbolAddress((void**)&oh,  g_oh2);
    cudaGetSymbolAddress((void**)&ol,  g_ol2);
    cudaGetSymbolAddress((void**)&wqh, g_wqh);
    cudaGetSymbolAddress((void**)&wph, g_wph);

    cudaFuncSetAttribute(mma_gemm4,
                         cudaFuncAttributeMaxDynamicSharedMemorySize, G4_SMEM);

    // 0) trig table + operand prepasses
    trig_table<<<(TSEQ * 32 + 255) / 256, 256>>>();
    const int xpairs = TOKENS * DIM / 2;
    split_pairs_rows<<<(xpairs + 255) / 256, 256>>>(x, xh, xl, xpairs);
    pack_pairs_cols<<<((DIM / 2) * QKV_N + 255) / 256, 256>>>(w_qkv, wqh, QKV_N, DIM);
    pack_pairs_cols<<<((DIM / 2) * DIM + 255) / 256, 256>>>(w_proj, wph, DIM, DIM);

    // 1) qkv = x @ w_qkv -> g_q/g_k/g_v
    mma_gemm4<<<dim3(QKV_N / 128, TOKENS / 128), 256, G4_SMEM>>>(
        xh, xl, wqh, nullptr, nullptr, QKV_N, DIM, 1);

    // 2) rope + pack
    rope_split<<<(BHEADS * TSEQ * 32 + 255) / 256, 256>>>();

    // 3) V transpose + pack
    v_transpose<<<dim3(TSEQ / 64, BHEADS), 256>>>();

    // 4) flash attention (fp16 2-pass tensor cores)
    flash_mma<<<dim3(TSEQ / 128, BHEADS), 256>>>();

    // 5) out = g_o @ w_proj + b_proj
    split_pairs_rows<<<(xpairs + 255) / 256, 256>>>(o_p, oh, ol, xpairs);
    mma_gemm4<<<dim3(DIM / 128, TOKENS / 128), 256, G4_SMEM>>>(
        oh, ol, wph, out, b_proj, DIM, DIM, 0);
}

// round 11
// speedup vs baseline: 3.3908x; 1.0404x over previous
#include <cuda_runtime.h>
#include <cuda_fp16.h>
#include <stdint.h>
#include <math.h>

typedef unsigned int u32;

#define TOKENS 4096
#define DIM    1024
#define QKV_N  3072
#define NH     16
#define HD     64
#define TSEQ   2048
#define BHEADS 32
// 0.125 * log2(e)
#define SCALE2 0.18033688011112042f

// ---------------- global scratch ----------------
__device__ float g_q[BHEADS * TSEQ * HD];   // [bh][t][d] (pre-rope fp32)
__device__ float g_k[BHEADS * TSEQ * HD];
__device__ float g_v[BHEADS * TSEQ * HD];
__device__ float g_o[TOKENS * DIM];         // token-major

__device__ float2 g_trig[TSEQ * 32];

// GEMM A operands: [M][K2] u32 (fp16 pairs along K), hi+lo split
__device__ u32 g_xh[TOKENS * DIM / 2],  g_xl[TOKENS * DIM / 2];
__device__ u32 g_oh2[TOKENS * DIM / 2], g_ol2[TOKENS * DIM / 2];
// GEMM B operands: [K2][N] u32 (fp16 pairs along K), rounded single
__device__ u32 g_wqh[DIM / 2 * QKV_N];
__device__ u32 g_wph[DIM / 2 * DIM];

// flash operands: Q split hi/lo, K/V rounded single (fp16 pairs)
__device__ u32 g_qh[BHEADS * TSEQ * 32], g_ql[BHEADS * TSEQ * 32];
__device__ u32 g_kh[BHEADS * TSEQ * 32];
__device__ u32 g_vth[BHEADS * HD * (TSEQ / 2)];

// ---------------- helpers ----------------
__device__ __forceinline__ void mma_f16(float c[4],
                                        const u32 a[4], const u32 b[2])
{
    asm volatile(
        "mma.sync.aligned.m16n8k16.row.col.f32.f16.f16.f32 "
        "{%0,%1,%2,%3}, {%4,%5,%6,%7}, {%8,%9}, {%0,%1,%2,%3};"
        : "+f"(c[0]), "+f"(c[1]), "+f"(c[2]), "+f"(c[3])
        : "r"(a[0]), "r"(a[1]), "r"(a[2]), "r"(a[3]),
          "r"(b[0]), "r"(b[1]));
}

__device__ __forceinline__ void split_pack_f16(float x0, float x1,
                                               u32& hi, u32& lo)
{
    __half2 H = __floats2half2_rn(x0, x1);
    float2 hf = __half22float2(H);
    __half2 L = __floats2half2_rn(x0 - hf.x, x1 - hf.y);
    hi = *(u32*)&H;
    lo = *(u32*)&L;
}

__device__ __forceinline__ u32 pack_f16(float x0, float x1)
{
    __half2 H = __floats2half2_rn(x0, x1);
    return *(u32*)&H;
}

// FFMA-only exp2 (no MUFU)
__device__ __forceinline__ float exp2_fast(float x)
{
    x = fmaxf(x, -60.0f);
    float t  = __fadd_rn(x, 12582912.0f);
    int   n  = __float_as_int(t) << 23;
    float ni = __fadd_rn(t, -12582912.0f);
    float r  = __fadd_rn(x, -ni);
    float p  = 1.3333558e-3f;
    p = fmaf(p, r, 9.6181291e-3f);
    p = fmaf(p, r, 5.5504109e-2f);
    p = fmaf(p, r, 2.4022651e-1f);
    p = fmaf(p, r, 6.9314718e-1f);
    p = fmaf(p, r, 1.0f);
    return __int_as_float(__float_as_int(p) + n);
}

__device__ __forceinline__ void cp16(u32* smem_dst, const u32* gsrc)
{
    unsigned d = (unsigned)__cvta_generic_to_shared(smem_dst);
    asm volatile("cp.async.cg.shared.global [%0], [%1], 16;" :: "r"(d), "l"(gsrc));
}

// ---------------- prepass kernels ----------------
__global__ __launch_bounds__(256)
void split_pairs_rows(const float* __restrict__ src, u32* __restrict__ hi,
                      u32* __restrict__ lo, int npairs)
{
    int i = blockIdx.x * 256 + threadIdx.x;
    if (i >= npairs) return;
    float2 v = ((const float2*)src)[i];
    split_pack_f16(v.x, v.y, hi[i], lo[i]);
}

__global__ __launch_bounds__(256)
void pack_pairs_cols(const float* __restrict__ B, u32* __restrict__ hi,
                     int N, int K)
{
    int i = blockIdx.x * 256 + threadIdx.x;
    int K2 = K >> 1;
    if (i >= K2 * N) return;
    int k2 = i / N, n = i - k2 * N;
    hi[i] = pack_f16(B[(size_t)(2 * k2) * N + n],
                     B[(size_t)(2 * k2 + 1) * N + n]);
}

// ---------------------------------------------------------------------------
// mma_gemm5: fp16 A-split 2-pass GEMM, 3-stage cp.async pipeline, 2 CTAs/SM.
// A: [M][K2] hi/lo. B: [K2][N] single. Tile 128x128, BK=32 (16 pairs).
// Prefetch issued before compute each stage: load(c+2) overlaps compute(c,c+1).
// ---------------------------------------------------------------------------
#define A_ST  (128 * 20)        // u32 per A array per stage
#define B_ST  (16 * 136)        // u32 per B array per stage
#define STG_U32 (2 * A_ST + B_ST)
#define G5_SMEM (3 * STG_U32 * 4)    // 87552 bytes

__global__ __launch_bounds__(256, 2)
void mma_gemm5(const u32* __restrict__ Agh, const u32* __restrict__ Agl,
               const u32* __restrict__ Bgh,
               float* __restrict__ C, const float* __restrict__ bias,
               int N, int K, int epi)
{
    extern __shared__ u32 sm5[];

    const int tid  = threadIdx.x;
    const int wid  = tid >> 5;
    const int lane = tid & 31;
    const int r8   = lane >> 2;
    const int c4   = lane & 3;
    const int wm   = (wid >> 2) * 64;
    const int wn   = (wid & 3) * 32;
    const int brow = blockIdx.y, bcol = blockIdx.x;
    const int K2   = K >> 1;

    const int ar  = tid & 127;
    const int acb = (tid >> 7) * 8;
    const u32* Aph = Agh + (size_t)(brow * 128 + ar) * K2 + acb;
    const u32* Apl = Agl + (size_t)(brow * 128 + ar) * K2 + acb;
    const int bk  = tid >> 4;
    const int bnc = (tid & 15) * 8;
    const u32* Bph = Bgh + (size_t)bk * N + bcol * 128 + bnc;

    float acc[4][4][4];
    #pragma unroll
    for (int i = 0; i < 4; i++)
        #pragma unroll
        for (int j = 0; j < 4; j++)
            #pragma unroll
            for (int r = 0; r < 4; r++) acc[i][j][r] = 0.f;

    auto issue = [&](int k2base, int s) {
        u32* st = sm5 + s * STG_U32;
        u32* aH = st + ar * 20 + acb;
        u32* aL = st + A_ST + ar * 20 + acb;
        cp16(aH,     Aph + k2base);
        cp16(aH + 4, Aph + k2base + 4);
        cp16(aL,     Apl + k2base);
        cp16(aL + 4, Apl + k2base + 4);
        u32* bH = st + 2 * A_ST + bk * 136 + bnc;
        cp16(bH,     Bph + (size_t)k2base * N);
        cp16(bH + 4, Bph + (size_t)k2base * N + 4);
        asm volatile("cp.async.commit_group;");
    };

    issue(0, 0);
    issue(16, 1);

    const int nst = K2 >> 4;   // stages of 16 pairs (BK=32)
    int s = 0;
    for (int ks = 0; ks < nst; ks++) {
        asm volatile("cp.async.wait_group 1;");
        __syncthreads();
        if (ks + 2 < nst) {
            int s2 = s + 2; if (s2 >= 3) s2 -= 3;
            issue((ks + 2) * 16, s2);
        } else {
            asm volatile("cp.async.commit_group;");
        }

        const u32* st = sm5 + s * STG_U32;
        const u32* aH = st;
        const u32* aL = st + A_ST;
        const u32* bH = st + 2 * A_ST;

        #pragma unroll
        for (int kk = 0; kk < 2; kk++) {
            const int kc = kk * 8 + c4;
            u32 bh[4][2];
            #pragma unroll
            for (int nf = 0; nf < 4; nf++) {
                const int n = wn + nf * 8 + r8;
                bh[nf][0] = bH[kc * 136 + n];
                bh[nf][1] = bH[(kc + 4) * 136 + n];
            }
            #pragma unroll
            for (int mf = 0; mf < 4; mf++) {
                const int m = wm + mf * 16 + r8;
                u32 ah[4], al[4];
                ah[0] = aH[m * 20 + kc];
                ah[1] = aH[(m + 8) * 20 + kc];
                ah[2] = aH[m * 20 + kc + 4];
                ah[3] = aH[(m + 8) * 20 + kc + 4];
                al[0] = aL[m * 20 + kc];
                al[1] = aL[(m + 8) * 20 + kc];
                al[2] = aL[m * 20 + kc + 4];
                al[3] = aL[(m + 8) * 20 + kc + 4];
                #pragma unroll
                for (int nf = 0; nf < 4; nf++) {
                    mma_f16(acc[mf][nf], ah, bh[nf]);
                    mma_f16(acc[mf][nf], al, bh[nf]);
                }
            }
        }
        if (++s >= 3) s -= 3;
    }

    if (!epi) {
        #pragma unroll
        for (int nf = 0; nf < 4; nf++) {
            const int cg = bcol * 128 + wn + nf * 8 + c4 * 2;
            float bx = bias ? bias[cg]     : 0.f;
            float by = bias ? bias[cg + 1] : 0.f;
            #pragma unroll
            for (int mf = 0; mf < 4; mf++) {
                const int rg = brow * 128 + wm + mf * 16 + r8;
                float2 v0 = make_float2(acc[mf][nf][0] + bx, acc[mf][nf][1] + by);
                float2 v1 = make_float2(acc[mf][nf][2] + bx, acc[mf][nf][3] + by);
                *(float2*)(C + (size_t)rg * N + cg)       = v0;
                *(float2*)(C + (size_t)(rg + 8) * N + cg) = v1;
            }
        }
    } else {
        #pragma unroll
        for (int nf = 0; nf < 4; nf++) {
            const int n_g   = bcol * 128 + wn + nf * 8 + c4 * 2;
            const int which = n_g >> 10;
            const int rmod  = n_g & 1023;
            const int h     = rmod >> 6;
            const int d     = rmod & 63;
            float* base = (which == 0) ? g_q : (which == 1) ? g_k : g_v;
            #pragma unroll
            for (int mf = 0; mf < 4; mf++) {
                const int m_g0 = brow * 128 + wm + mf * 16 + r8;
                #pragma unroll
                for (int half = 0; half < 2; half++) {
                    const int m_g = m_g0 + half * 8;
                    const int b   = m_g >> 11;
                    const int t   = m_g & 2047;
                    float2 v = make_float2(acc[mf][nf][half * 2],
                                           acc[mf][nf][half * 2 + 1]);
                    *(float2*)(base + (((size_t)(b * 16 + h) * TSEQ + t) * HD + d)) = v;
                }
            }
        }
    }
}

// ---------------------------------------------------------------------------
__global__ __launch_bounds__(256)
void trig_table()
{
    int idx = blockIdx.x * 256 + threadIdx.x;
    if (idx >= TSEQ * 32) return;
    int t = idx >> 5, i = idx & 31;
    float freq = expf(-9.210340371976184f * (float)i * (1.0f / 32.0f));
    float ang = (float)t * freq;
    float s, c;
    sincosf(ang, &s, &c);
    g_trig[idx] = make_float2(s, c);
}

// ---------------------------------------------------------------------------
__global__ __launch_bounds__(256)
void rope_split()
{
    int gw   = (blockIdx.x * 256 + threadIdx.x) >> 5;
    int lane = threadIdx.x & 31;
    if (gw >= BHEADS * TSEQ) return;
    int bh = gw >> 11;
    int t  = gw & 2047;

    float2 sc = g_trig[t * 32 + lane];
    float s = sc.x, c = sc.y;

    size_t off = ((size_t)bh * TSEQ + t) * HD;

    float q1 = g_q[off + lane], q2 = g_q[off + lane + 32];
    float qa = (q1 * c - q2 * s) * SCALE2;
    float qb = (q1 * s + q2 * c) * SCALE2;

    float k1 = g_k[off + lane], k2 = g_k[off + lane + 32];
    float ka = k1 * c - k2 * s;
    float kb = k1 * s + k2 * c;

    int src = (2 * lane) & 31;
    float qa0 = __shfl_sync(0xffffffffu, qa, src);
    float qa1 = __shfl_sync(0xffffffffu, qa, src + 1);
    float qb0 = __shfl_sync(0xffffffffu, qb, src);
    float qb1 = __shfl_sync(0xffffffffu, qb, src + 1);
    float ka0 = __shfl_sync(0xffffffffu, ka, src);
    float ka1 = __shfl_sync(0xffffffffu, ka, src + 1);
    float kb0 = __shfl_sync(0xffffffffu, kb, src);
    float kb1 = __shfl_sync(0xffffffffu, kb, src + 1);

    float e0 = (lane < 16) ? qa0 : qb0;
    float e1 = (lane < 16) ? qa1 : qb1;
    u32 hi, lo;
    split_pack_f16(e0, e1, hi, lo);
    size_t po = ((size_t)bh * TSEQ + t) * 32 + lane;
    g_qh[po] = hi;
    g_ql[po] = lo;

    e0 = (lane < 16) ? ka0 : kb0;
    e1 = (lane < 16) ? ka1 : kb1;
    g_kh[po] = pack_f16(e0, e1);
}

// ---------------------------------------------------------------------------
__global__ __launch_bounds__(256)
void v_transpose()
{
    __shared__ float sv[64][65];
    const int bh = blockIdx.y, tb = blockIdx.x;
    const int tid = threadIdx.x;

    {
        int r = tid >> 2, cb = (tid & 3) * 16;
        const float* vp = g_v + ((size_t)bh * TSEQ + tb * 64 + r) * HD + cb;
        #pragma unroll
        for (int i = 0; i < 16; i += 4) {
            float4 v = *(const float4*)(vp + i);
            sv[r][cb + i + 0] = v.x;
            sv[r][cb + i + 1] = v.y;
            sv[r][cb + i + 2] = v.z;
            sv[r][cb + i + 3] = v.w;
        }
    }
    __syncthreads();

    int t2 = tid & 31, dbase = (tid >> 5) * 8;
    #pragma unroll
    for (int i = 0; i < 8; i++) {
        int d = dbase + i;
        size_t o = ((size_t)bh * HD + d) * (TSEQ / 2) + tb * 32 + t2;
        g_vth[o] = pack_f16(sv[2 * t2][d], sv[2 * t2 + 1][d]);
    }
}

// ---------------------------------------------------------------------------
// Flash attention: fp16 2-pass, cp.async double-buffered K/V, exp2 softmax.
// BQ=128 (8 warps x 16 rows), BK=64, 256 threads.
// ---------------------------------------------------------------------------
#define FKS  36
#define FTILE (64 * FKS)

__global__ __launch_bounds__(256)
void flash_mma()
{
    __shared__ u32 Ksh[2 * FTILE];
    __shared__ u32 Vsh[2 * FTILE];

    const int bh   = blockIdx.y;
    const int qblk = gridDim.x - 1 - blockIdx.x;
    const int q0   = qblk * 128;

    const int tid  = threadIdx.x;
    const int w    = tid >> 5;
    const int lane = tid & 31;
    const int r8   = lane >> 2;
    const int c4   = lane & 3;

    u32 qh[4][4], ql[4][4];
    {
        const u32* Qh = g_qh + ((size_t)bh * TSEQ + q0 + w * 16) * 32;
        const u32* Ql = g_ql + ((size_t)bh * TSEQ + q0 + w * 16) * 32;
        #pragma unroll
        for (int g = 0; g < 4; g++) {
            qh[g][0] = Qh[(size_t)r8 * 32 + 8 * g + c4];
            qh[g][1] = Qh[(size_t)(r8 + 8) * 32 + 8 * g + c4];
            qh[g][2] = Qh[(size_t)r8 * 32 + 8 * g + c4 + 4];
            qh[g][3] = Qh[(size_t)(r8 + 8) * 32 + 8 * g + c4 + 4];
            ql[g][0] = Ql[(size_t)r8 * 32 + 8 * g + c4];
            ql[g][1] = Ql[(size_t)(r8 + 8) * 32 + 8 * g + c4];
            ql[g][2] = Ql[(size_t)r8 * 32 + 8 * g + c4 + 4];
            ql[g][3] = Ql[(size_t)(r8 + 8) * 32 + 8 * g + c4 + 4];
        }
    }

    float oacc[8][4];
    #pragma unroll
    for (int i = 0; i < 8; i++)
        #pragma unroll
        for (int j = 0; j < 4; j++) oacc[i][j] = 0.f;
    float m0 = -1e30f, m1 = -1e30f, l0 = 0.f, l1 = 0.f;

    const int row0 = q0 + w * 16 + r8;
    const int row1 = row0 + 8;

    const u32* Kgh = g_kh + (size_t)bh * TSEQ * 32;
    const u32* Vgh = g_vth + (size_t)bh * HD * (TSEQ / 2);

    const int lr = tid >> 2, lcb = (tid & 3) * 8;

    auto fissue = [&](int tile, int s) {
        const int k0 = tile * 64;
        const u32* kh = Kgh + (size_t)(k0 + lr) * 32 + lcb;
        const u32* vh = Vgh + (size_t)lr * (TSEQ / 2) + (k0 >> 1) + lcb;
        u32* dk = Ksh + s * FTILE + lr * FKS + lcb;
        u32* dv = Vsh + s * FTILE + lr * FKS + lcb;
        cp16(dk,     kh);
        cp16(dk + 4, kh + 4);
        cp16(dv,     vh);
        cp16(dv + 4, vh + 4);
        asm volatile("cp.async.commit_group;");
    };

    const int ntiles = 2 * qblk + 2;
    fissue(0, 0);

    for (int tile = 0; tile < ntiles; tile++) {
        asm volatile("cp.async.wait_group 0;");
        __syncthreads();
        if (tile + 1 < ntiles) fissue(tile + 1, (tile + 1) & 1);

        const int sb = (tile & 1) * FTILE;
        const int k0 = tile * 64;

        const bool active = (k0 <= q0 + w * 16 + 15);
        if (active) {
            float sacc[8][4];
            #pragma unroll
            for (int i = 0; i < 8; i++)
                #pragma unroll
                for (int j = 0; j < 4; j++) sacc[i][j] = 0.f;

            #pragma unroll
            for (int g = 0; g < 4; g++) {
                #pragma unroll
                for (int nf = 0; nf < 8; nf++) {
                    const int base = sb + (nf * 8 + r8) * FKS + 8 * g + c4;
                    u32 bhx[2];
                    bhx[0] = Ksh[base]; bhx[1] = Ksh[base + 4];
                    mma_f16(sacc[nf], qh[g], bhx);
                    mma_f16(sacc[nf], ql[g], bhx);
                }
            }

            if (k0 + 63 > row0) {
                #pragma unroll
                for (int nf = 0; nf < 8; nf++) {
                    const int n0 = k0 + nf * 8 + 2 * c4;
                    if (n0 > row0)     sacc[nf][0] = -1e30f;
                    if (n0 + 1 > row0) sacc[nf][1] = -1e30f;
                    if (n0 > row1)     sacc[nf][2] = -1e30f;
                    if (n0 + 1 > row1) sacc[nf][3] = -1e30f;
                }
            }

            float rm0 = -1e30f, rm1 = -1e30f;
            #pragma unroll
            for (int nf = 0; nf < 8; nf++) {
                rm0 = fmaxf(rm0, fmaxf(sacc[nf][0], sacc[nf][1]));
                rm1 = fmaxf(rm1, fmaxf(sacc[nf][2], sacc[nf][3]));
            }
            rm0 = fmaxf(rm0, __shfl_xor_sync(0xffffffffu, rm0, 1));
            rm0 = fmaxf(rm0, __shfl_xor_sync(0xffffffffu, rm0, 2));
            rm1 = fmaxf(rm1, __shfl_xor_sync(0xffffffffu, rm1, 1));
            rm1 = fmaxf(rm1, __shfl_xor_sync(0xffffffffu, rm1, 2));

            const float mn0 = fmaxf(m0, rm0);
            const float mn1 = fmaxf(m1, rm1);
            const float rs0 = exp2_fast(m0 - mn0);
            const float rs1 = exp2_fast(m1 - mn1);
            m0 = mn0; m1 = mn1;

            float sum0 = 0.f, sum1 = 0.f;
            #pragma unroll
            for (int nf = 0; nf < 8; nf++) {
                sacc[nf][0] = exp2_fast(sacc[nf][0] - mn0);
                sacc[nf][1] = exp2_fast(sacc[nf][1] - mn0);
                sacc[nf][2] = exp2_fast(sacc[nf][2] - mn1);
                sacc[nf][3] = exp2_fast(sacc[nf][3] - mn1);
                sum0 += sacc[nf][0] + sacc[nf][1];
                sum1 += sacc[nf][2] + sacc[nf][3];
            }
            sum0 += __shfl_xor_sync(0xffffffffu, sum0, 1);
            sum0 += __shfl_xor_sync(0xffffffffu, sum0, 2);
            sum1 += __shfl_xor_sync(0xffffffffu, sum1, 1);
            sum1 += __shfl_xor_sync(0xffffffffu, sum1, 2);
            l0 = l0 * rs0 + sum0;
            l1 = l1 * rs1 + sum1;

            #pragma unroll
            for (int nf = 0; nf < 8; nf++) {
                oacc[nf][0] *= rs0;
                oacc[nf][1] *= rs0;
                oacc[nf][2] *= rs1;
                oacc[nf][3] *= rs1;
            }

            #pragma unroll
            for (int g = 0; g < 4; g++) {
                u32 ph[4], pl[4];
                split_pack_f16(sacc[2 * g][0],     sacc[2 * g][1],     ph[0], pl[0]);
                split_pack_f16(sacc[2 * g][2],     sacc[2 * g][3],     ph[1], pl[1]);
                split_pack_f16(sacc[2 * g + 1][0], sacc[2 * g + 1][1], ph[2], pl[2]);
                split_pack_f16(sacc[2 * g + 1][2], sacc[2 * g + 1][3], ph[3], pl[3]);
                #pragma unroll
                for (int nf = 0; nf < 8; nf++) {
                    const int base = sb + (nf * 8 + r8) * FKS + 8 * g + c4;
                    u32 bhx[2];
                    bhx[0] = Vsh[base]; bhx[1] = Vsh[base + 4];
                    mma_f16(oacc[nf], ph, bhx);
                    mma_f16(oacc[nf], pl, bhx);
                }
            }
        }
    }

    const float inv0 = 1.0f / l0;
    const float inv1 = 1.0f / l1;
    const int b = bh >> 4, h = bh & 15;
    #pragma unroll
    for (int nf = 0; nf < 8; nf++) {
        const int d = nf * 8 + 2 * c4;
        float2 v0 = make_float2(oacc[nf][0] * inv0, oacc[nf][1] * inv0);
        float2 v1 = make_float2(oacc[nf][2] * inv1, oacc[nf][3] * inv1);
        *(float2*)(g_o + ((size_t)(b * TSEQ) + row0) * DIM + h * HD + d) = v0;
        *(float2*)(g_o + ((size_t)(b * TSEQ) + row1) * DIM + h * HD + d) = v1;
    }
}

// ---------------------------------------------------------------------------
extern "C" void kernel_launch(void* const* d_in, const int* in_sizes, int n_in,
                              void* d_out, int out_size)
{
    const float* x      = (const float*)d_in[0];
    const float* w_qkv  = (const float*)d_in[1];
    const float* w_proj = (const float*)d_in[2];
    const float* b_proj = (const float*)d_in[3];
    float* out = (float*)d_out;

    float* o_p = nullptr;
    cudaGetSymbolAddress((void**)&o_p, g_o);
    u32 *xh, *xl, *oh, *ol, *wqh, *wph;
    cudaGetSymbolAddress((void**)&xh,  g_xh);
    cudaGetSymbolAddress((void**)&xl,  g_xl);
    cudaGetSymbolAddress((void**)&oh,  g_oh2);
    cudaGetSymbolAddress((void**)&ol,  g_ol2);
    cudaGetSymbolAddress((void**)&wqh, g_wqh);
    cudaGetSymbolAddress((void**)&wph, g_wph);

    cudaFuncSetAttribute(mma_gemm5,
                         cudaFuncAttributeMaxDynamicSharedMemorySize, G5_SMEM);

    // 0) trig table + operand prepasses
    trig_table<<<(TSEQ * 32 + 255) / 256, 256>>>();
    const int xpairs = TOKENS * DIM / 2;
    split_pairs_rows<<<(xpairs + 255) / 256, 256>>>(x, xh, xl, xpairs);
    pack_pairs_cols<<<((DIM / 2) * QKV_N + 255) / 256, 256>>>(w_qkv, wqh, QKV_N, DIM);
    pack_pairs_cols<<<((DIM / 2) * DIM + 255) / 256, 256>>>(w_proj, wph, DIM, DIM);

    // 1) qkv = x @ w_qkv -> g_q/g_k/g_v
    mma_gemm5<<<dim3(QKV_N / 128, TOKENS / 128), 256, G5_SMEM>>>(
        xh, xl, wqh, nullptr, nullptr, QKV_N, DIM, 1);

    // 2) rope + pack
    rope_split<<<(BHEADS * TSEQ * 32 + 255) / 256, 256>>>();

    // 3) V transpose + pack
    v_transpose<<<dim3(TSEQ / 64, BHEADS), 256>>>();

    // 4) flash attention (fp16 2-pass, double-buffered)
    flash_mma<<<dim3(TSEQ / 128, BHEADS), 256>>>();

    // 5) out = g_o @ w_proj + b_proj
    split_pairs_rows<<<(xpairs + 255) / 256, 256>>>(o_p, oh, ol, xpairs);
    mma_gemm5<<<dim3(DIM / 128, TOKENS / 128), 256, G5_SMEM>>>(
        oh, ol, wph, out, b_proj, DIM, DIM, 0);
}

// round 12
// speedup vs baseline: 3.5590x; 1.0496x over previous
#include <cuda_runtime.h>
#include <cuda_fp16.h>
#include <stdint.h>
#include <math.h>

typedef unsigned int u32;

#define TOKENS 4096
#define DIM    1024
#define QKV_N  3072
#define NH     16
#define HD     64
#define TSEQ   2048
#define BHEADS 32
// 0.125 * log2(e)
#define SCALE2 0.18033688011112042f

// ---------------- global scratch ----------------
__device__ float g_q[BHEADS * TSEQ * HD];   // [bh][t][d] (pre-rope fp32)
__device__ float g_k[BHEADS * TSEQ * HD];
__device__ float g_v[BHEADS * TSEQ * HD];
__device__ float g_o[TOKENS * DIM];         // token-major

__device__ float2 g_trig[TSEQ * 32];

// GEMM A operands: [M][K2] u32 (fp16 pairs along K), hi+lo split
__device__ u32 g_xh[TOKENS * DIM / 2],  g_xl[TOKENS * DIM / 2];
__device__ u32 g_oh2[TOKENS * DIM / 2], g_ol2[TOKENS * DIM / 2];
// GEMM B operands: [K2][N] u32 (fp16 pairs along K), rounded single
__device__ u32 g_wqh[DIM / 2 * QKV_N];
__device__ u32 g_wph[DIM / 2 * DIM];

// flash operands: Q split hi/lo, K/V rounded single (fp16 pairs)
__device__ u32 g_qh[BHEADS * TSEQ * 32], g_ql[BHEADS * TSEQ * 32];
__device__ u32 g_kh[BHEADS * TSEQ * 32];
__device__ u32 g_vth[BHEADS * HD * (TSEQ / 2)];

// ---------------- helpers ----------------
__device__ __forceinline__ void mma_f16(float c[4],
                                        const u32 a[4], const u32 b[2])
{
    asm volatile(
        "mma.sync.aligned.m16n8k16.row.col.f32.f16.f16.f32 "
        "{%0,%1,%2,%3}, {%4,%5,%6,%7}, {%8,%9}, {%0,%1,%2,%3};"
        : "+f"(c[0]), "+f"(c[1]), "+f"(c[2]), "+f"(c[3])
        : "r"(a[0]), "r"(a[1]), "r"(a[2]), "r"(a[3]),
          "r"(b[0]), "r"(b[1]));
}

__device__ __forceinline__ void ldsm_x4(u32 r[4], u32 saddr)
{
    asm volatile(
        "ldmatrix.sync.aligned.m8n8.x4.shared.b16 {%0,%1,%2,%3}, [%4];"
        : "=r"(r[0]), "=r"(r[1]), "=r"(r[2]), "=r"(r[3]) : "r"(saddr));
}

__device__ __forceinline__ void split_pack_f16(float x0, float x1,
                                               u32& hi, u32& lo)
{
    __half2 H = __floats2half2_rn(x0, x1);
    float2 hf = __half22float2(H);
    __half2 L = __floats2half2_rn(x0 - hf.x, x1 - hf.y);
    hi = *(u32*)&H;
    lo = *(u32*)&L;
}

__device__ __forceinline__ u32 pack_f16(float x0, float x1)
{
    __half2 H = __floats2half2_rn(x0, x1);
    return *(u32*)&H;
}

// FFMA-only exp2 (no MUFU)
__device__ __forceinline__ float exp2_fast(float x)
{
    x = fmaxf(x, -60.0f);
    float t  = __fadd_rn(x, 12582912.0f);
    int   n  = __float_as_int(t) << 23;
    float ni = __fadd_rn(t, -12582912.0f);
    float r  = __fadd_rn(x, -ni);
    float p  = 1.3333558e-3f;
    p = fmaf(p, r, 9.6181291e-3f);
    p = fmaf(p, r, 5.5504109e-2f);
    p = fmaf(p, r, 2.4022651e-1f);
    p = fmaf(p, r, 6.9314718e-1f);
    p = fmaf(p, r, 1.0f);
    return __int_as_float(__float_as_int(p) + n);
}

__device__ __forceinline__ void cp16(u32* smem_dst, const u32* gsrc)
{
    unsigned d = (unsigned)__cvta_generic_to_shared(smem_dst);
    asm volatile("cp.async.cg.shared.global [%0], [%1], 16;" :: "r"(d), "l"(gsrc));
}

// ---------------- prepass kernels ----------------
__global__ __launch_bounds__(256)
void split_pairs_rows(const float* __restrict__ src, u32* __restrict__ hi,
                      u32* __restrict__ lo, int npairs)
{
    int i = blockIdx.x * 256 + threadIdx.x;
    if (i >= npairs) return;
    float2 v = ((const float2*)src)[i];
    split_pack_f16(v.x, v.y, hi[i], lo[i]);
}

__global__ __launch_bounds__(256)
void pack_pairs_cols(const float* __restrict__ B, u32* __restrict__ hi,
                     int N, int K)
{
    int i = blockIdx.x * 256 + threadIdx.x;
    int K2 = K >> 1;
    if (i >= K2 * N) return;
    int k2 = i / N, n = i - k2 * N;
    hi[i] = pack_f16(B[(size_t)(2 * k2) * N + n],
                     B[(size_t)(2 * k2 + 1) * N + n]);
}

// ---------------------------------------------------------------------------
// mma_gemm6: fp16 A-split 2-pass GEMM, 3-stage cp.async, ldmatrix A-frags.
// A: [M][K2] hi/lo. B: [K2][N] single. Tile 128x128, BK=32 (16 pairs).
// ---------------------------------------------------------------------------
#define A_ST  (128 * 20)        // u32 per A array per stage
#define B_ST  (16 * 136)        // u32 per B array per stage
#define STG_U32 (2 * A_ST + B_ST)
#define G6_SMEM (3 * STG_U32 * 4)    // 87552 bytes

__global__ __launch_bounds__(256, 2)
void mma_gemm6(const u32* __restrict__ Agh, const u32* __restrict__ Agl,
               const u32* __restrict__ Bgh,
               float* __restrict__ C, const float* __restrict__ bias,
               int N, int K, int epi)
{
    extern __shared__ u32 sm6[];

    const int tid  = threadIdx.x;
    const int wid  = tid >> 5;
    const int lane = tid & 31;
    const int r8   = lane >> 2;
    const int c4   = lane & 3;
    const int grp  = lane >> 3;     // ldmatrix group 0..3
    const int wtn  = lane & 7;      // within-group row
    const int wm   = (wid >> 2) * 64;
    const int wn   = (wid & 3) * 32;
    const int brow = blockIdx.y, bcol = blockIdx.x;
    const int K2   = K >> 1;

    const u32 smbase = (u32)__cvta_generic_to_shared(sm6);
    // per-lane A ldmatrix offset (u32 units): row*(20) + colgroup*4
    const u32 lmA = (u32)(((grp & 1) * 8 + wtn) * 20 + (grp >> 1) * 4);

    const int ar  = tid & 127;
    const int acb = (tid >> 7) * 8;
    const u32* Aph = Agh + (size_t)(brow * 128 + ar) * K2 + acb;
    const u32* Apl = Agl + (size_t)(brow * 128 + ar) * K2 + acb;
    const int bk  = tid >> 4;
    const int bnc = (tid & 15) * 8;
    const u32* Bph = Bgh + (size_t)bk * N + bcol * 128 + bnc;

    float acc[4][4][4];
    #pragma unroll
    for (int i = 0; i < 4; i++)
        #pragma unroll
        for (int j = 0; j < 4; j++)
            #pragma unroll
            for (int r = 0; r < 4; r++) acc[i][j][r] = 0.f;

    auto issue = [&](int k2base, int s) {
        u32* st = sm6 + s * STG_U32;
        u32* aH = st + ar * 20 + acb;
        u32* aL = st + A_ST + ar * 20 + acb;
        cp16(aH,     Aph + k2base);
        cp16(aH + 4, Aph + k2base + 4);
        cp16(aL,     Apl + k2base);
        cp16(aL + 4, Apl + k2base + 4);
        u32* bH = st + 2 * A_ST + bk * 136 + bnc;
        cp16(bH,     Bph + (size_t)k2base * N);
        cp16(bH + 4, Bph + (size_t)k2base * N + 4);
        asm volatile("cp.async.commit_group;");
    };

    issue(0, 0);
    issue(16, 1);

    const int nst = K2 >> 4;
    int s = 0;
    for (int ks = 0; ks < nst; ks++) {
        asm volatile("cp.async.wait_group 1;");
        __syncthreads();
        if (ks + 2 < nst) {
            int s2 = s + 2; if (s2 >= 3) s2 -= 3;
            issue((ks + 2) * 16, s2);
        } else {
            asm volatile("cp.async.commit_group;");
        }

        const u32 stoff = (u32)(s * STG_U32);
        const u32 aHb = smbase + (stoff + lmA + wm * 20) * 4;
        const u32 aLb = aHb + A_ST * 4;
        const u32* bH = sm6 + stoff + 2 * A_ST;

        #pragma unroll
        for (int kk = 0; kk < 2; kk++) {
            const int kc = kk * 8 + c4;
            u32 bh[4][2];
            #pragma unroll
            for (int nf = 0; nf < 4; nf++) {
                const int n = wn + nf * 8 + r8;
                bh[nf][0] = bH[kc * 136 + n];
                bh[nf][1] = bH[(kc + 4) * 136 + n];
            }
            #pragma unroll
            for (int mf = 0; mf < 4; mf++) {
                u32 ah[4], al[4];
                const u32 moff = (u32)(mf * 16 * 20 + kk * 8) * 4;
                ldsm_x4(ah, aHb + moff);
                ldsm_x4(al, aLb + moff);
                #pragma unroll
                for (int nf = 0; nf < 4; nf++) {
                    mma_f16(acc[mf][nf], ah, bh[nf]);
                    mma_f16(acc[mf][nf], al, bh[nf]);
                }
            }
        }
        if (++s >= 3) s -= 3;
    }

    if (!epi) {
        #pragma unroll
        for (int nf = 0; nf < 4; nf++) {
            const int cg = bcol * 128 + wn + nf * 8 + c4 * 2;
            float bx = bias ? bias[cg]     : 0.f;
            float by = bias ? bias[cg + 1] : 0.f;
            #pragma unroll
            for (int mf = 0; mf < 4; mf++) {
                const int rg = brow * 128 + wm + mf * 16 + r8;
                float2 v0 = make_float2(acc[mf][nf][0] + bx, acc[mf][nf][1] + by);
                float2 v1 = make_float2(acc[mf][nf][2] + bx, acc[mf][nf][3] + by);
                *(float2*)(C + (size_t)rg * N + cg)       = v0;
                *(float2*)(C + (size_t)(rg + 8) * N + cg) = v1;
            }
        }
    } else {
        #pragma unroll
        for (int nf = 0; nf < 4; nf++) {
            const int n_g   = bcol * 128 + wn + nf * 8 + c4 * 2;
            const int which = n_g >> 10;
            const int rmod  = n_g & 1023;
            const int h     = rmod >> 6;
            const int d     = rmod & 63;
            float* base = (which == 0) ? g_q : (which == 1) ? g_k : g_v;
            #pragma unroll
            for (int mf = 0; mf < 4; mf++) {
                const int m_g0 = brow * 128 + wm + mf * 16 + r8;
                #pragma unroll
                for (int half = 0; half < 2; half++) {
                    const int m_g = m_g0 + half * 8;
                    const int b   = m_g >> 11;
                    const int t   = m_g & 2047;
                    float2 v = make_float2(acc[mf][nf][half * 2],
                                           acc[mf][nf][half * 2 + 1]);
                    *(float2*)(base + (((size_t)(b * 16 + h) * TSEQ + t) * HD + d)) = v;
                }
            }
        }
    }
}

// ---------------------------------------------------------------------------
__global__ __launch_bounds__(256)
void trig_table()
{
    int idx = blockIdx.x * 256 + threadIdx.x;
    if (idx >= TSEQ * 32) return;
    int t = idx >> 5, i = idx & 31;
    float freq = expf(-9.210340371976184f * (float)i * (1.0f / 32.0f));
    float ang = (float)t * freq;
    float s, c;
    sincosf(ang, &s, &c);
    g_trig[idx] = make_float2(s, c);
}

// ---------------------------------------------------------------------------
__global__ __launch_bounds__(256)
void rope_split()
{
    int gw   = (blockIdx.x * 256 + threadIdx.x) >> 5;
    int lane = threadIdx.x & 31;
    if (gw >= BHEADS * TSEQ) return;
    int bh = gw >> 11;
    int t  = gw & 2047;

    float2 sc = g_trig[t * 32 + lane];
    float s = sc.x, c = sc.y;

    size_t off = ((size_t)bh * TSEQ + t) * HD;

    float q1 = g_q[off + lane], q2 = g_q[off + lane + 32];
    float qa = (q1 * c - q2 * s) * SCALE2;
    float qb = (q1 * s + q2 * c) * SCALE2;

    float k1 = g_k[off + lane], k2 = g_k[off + lane + 32];
    float ka = k1 * c - k2 * s;
    float kb = k1 * s + k2 * c;

    int src = (2 * lane) & 31;
    float qa0 = __shfl_sync(0xffffffffu, qa, src);
    float qa1 = __shfl_sync(0xffffffffu, qa, src + 1);
    float qb0 = __shfl_sync(0xffffffffu, qb, src);
    float qb1 = __shfl_sync(0xffffffffu, qb, src + 1);
    float ka0 = __shfl_sync(0xffffffffu, ka, src);
    float ka1 = __shfl_sync(0xffffffffu, ka, src + 1);
    float kb0 = __shfl_sync(0xffffffffu, kb, src);
    float kb1 = __shfl_sync(0xffffffffu, kb, src + 1);

    float e0 = (lane < 16) ? qa0 : qb0;
    float e1 = (lane < 16) ? qa1 : qb1;
    u32 hi, lo;
    split_pack_f16(e0, e1, hi, lo);
    size_t po = ((size_t)bh * TSEQ + t) * 32 + lane;
    g_qh[po] = hi;
    g_ql[po] = lo;

    e0 = (lane < 16) ? ka0 : kb0;
    e1 = (lane < 16) ? ka1 : kb1;
    g_kh[po] = pack_f16(e0, e1);
}

// ---------------------------------------------------------------------------
__global__ __launch_bounds__(256)
void v_transpose()
{
    __shared__ float sv[64][65];
    const int bh = blockIdx.y, tb = blockIdx.x;
    const int tid = threadIdx.x;

    {
        int r = tid >> 2, cb = (tid & 3) * 16;
        const float* vp = g_v + ((size_t)bh * TSEQ + tb * 64 + r) * HD + cb;
        #pragma unroll
        for (int i = 0; i < 16; i += 4) {
            float4 v = *(const float4*)(vp + i);
            sv[r][cb + i + 0] = v.x;
            sv[r][cb + i + 1] = v.y;
            sv[r][cb + i + 2] = v.z;
            sv[r][cb + i + 3] = v.w;
        }
    }
    __syncthreads();

    int t2 = tid & 31, dbase = (tid >> 5) * 8;
    #pragma unroll
    for (int i = 0; i < 8; i++) {
        int d = dbase + i;
        size_t o = ((size_t)bh * HD + d) * (TSEQ / 2) + tb * 32 + t2;
        g_vth[o] = pack_f16(sv[2 * t2][d], sv[2 * t2 + 1][d]);
    }
}

// ---------------------------------------------------------------------------
// Flash attention: fp16 2-pass, cp.async double-buffered, ldmatrix frags.
// ---------------------------------------------------------------------------
#define FKS  36
#define FTILE (64 * FKS)

__global__ __launch_bounds__(256)
void flash_mma()
{
    __shared__ u32 Ksh[2 * FTILE];
    __shared__ u32 Vsh[2 * FTILE];

    const int bh   = blockIdx.y;
    const int qblk = gridDim.x - 1 - blockIdx.x;
    const int q0   = qblk * 128;

    const int tid  = threadIdx.x;
    const int w    = tid >> 5;
    const int lane = tid & 31;
    const int r8   = lane >> 2;
    const int c4   = lane & 3;
    const int grp  = lane >> 3;
    const int wtn  = lane & 7;

    const u32 Kbase = (u32)__cvta_generic_to_shared(Ksh);
    const u32 Vbase = (u32)__cvta_generic_to_shared(Vsh);
    // per-lane ldmatrix offset: reg order {nf, nf(+4cols), nf+1, nf+1(+4cols)}
    const u32 lmF = (u32)(((grp >> 1) * 8 + wtn) * FKS + (grp & 1) * 4);

    u32 qh[4][4], ql[4][4];
    {
        const u32* Qh = g_qh + ((size_t)bh * TSEQ + q0 + w * 16) * 32;
        const u32* Ql = g_ql + ((size_t)bh * TSEQ + q0 + w * 16) * 32;
        #pragma unroll
        for (int g = 0; g < 4; g++) {
            qh[g][0] = Qh[(size_t)r8 * 32 + 8 * g + c4];
            qh[g][1] = Qh[(size_t)(r8 + 8) * 32 + 8 * g + c4];
            qh[g][2] = Qh[(size_t)r8 * 32 + 8 * g + c4 + 4];
            qh[g][3] = Qh[(size_t)(r8 + 8) * 32 + 8 * g + c4 + 4];
            ql[g][0] = Ql[(size_t)r8 * 32 + 8 * g + c4];
            ql[g][1] = Ql[(size_t)(r8 + 8) * 32 + 8 * g + c4];
            ql[g][2] = Ql[(size_t)r8 * 32 + 8 * g + c4 + 4];
            ql[g][3] = Ql[(size_t)(r8 + 8) * 32 + 8 * g + c4 + 4];
        }
    }

    float oacc[8][4];
    #pragma unroll
    for (int i = 0; i < 8; i++)
        #pragma unroll
        for (int j = 0; j < 4; j++) oacc[i][j] = 0.f;
    float m0 = -1e30f, m1 = -1e30f, l0 = 0.f, l1 = 0.f;

    const int row0 = q0 + w * 16 + r8;
    const int row1 = row0 + 8;

    const u32* Kgh = g_kh + (size_t)bh * TSEQ * 32;
    const u32* Vgh = g_vth + (size_t)bh * HD * (TSEQ / 2);

    const int lr = tid >> 2, lcb = (tid & 3) * 8;

    auto fissue = [&](int tile, int s) {
        const int k0 = tile * 64;
        const u32* kh = Kgh + (size_t)(k0 + lr) * 32 + lcb;
        const u32* vh = Vgh + (size_t)lr * (TSEQ / 2) + (k0 >> 1) + lcb;
        u32* dk = Ksh + s * FTILE + lr * FKS + lcb;
        u32* dv = Vsh + s * FTILE + lr * FKS + lcb;
        cp16(dk,     kh);
        cp16(dk + 4, kh + 4);
        cp16(dv,     vh);
        cp16(dv + 4, vh + 4);
        asm volatile("cp.async.commit_group;");
    };

    const int ntiles = 2 * qblk + 2;
    fissue(0, 0);

    for (int tile = 0; tile < ntiles; tile++) {
        asm volatile("cp.async.wait_group 0;");
        __syncthreads();
        if (tile + 1 < ntiles) fissue(tile + 1, (tile + 1) & 1);

        const u32 sboff = (u32)((tile & 1) * FTILE);
        const int k0 = tile * 64;

        const bool active = (k0 <= q0 + w * 16 + 15);
        if (active) {
            float sacc[8][4];
            #pragma unroll
            for (int i = 0; i < 8; i++)
                #pragma unroll
                for (int j = 0; j < 4; j++) sacc[i][j] = 0.f;

            const u32 kfb = Kbase + (sboff + lmF) * 4;
            #pragma unroll
            for (int g = 0; g < 4; g++) {
                #pragma unroll
                for (int nfp = 0; nfp < 4; nfp++) {
                    u32 kf[4];
                    ldsm_x4(kf, kfb + (u32)(nfp * 16 * FKS + 8 * g) * 4);
                    mma_f16(sacc[2 * nfp],     qh[g], kf);
                    mma_f16(sacc[2 * nfp],     ql[g], kf);
                    mma_f16(sacc[2 * nfp + 1], qh[g], kf + 2);
                    mma_f16(sacc[2 * nfp + 1], ql[g], kf + 2);
                }
            }

            if (k0 + 63 > row0) {
                #pragma unroll
                for (int nf = 0; nf < 8; nf++) {
                    const int n0 = k0 + nf * 8 + 2 * c4;
                    if (n0 > row0)     sacc[nf][0] = -1e30f;
                    if (n0 + 1 > row0) sacc[nf][1] = -1e30f;
                    if (n0 > row1)     sacc[nf][2] = -1e30f;
                    if (n0 + 1 > row1) sacc[nf][3] = -1e30f;
                }
            }

            float rm0 = -1e30f, rm1 = -1e30f;
            #pragma unroll
            for (int nf = 0; nf < 8; nf++) {
                rm0 = fmaxf(rm0, fmaxf(sacc[nf][0], sacc[nf][1]));
                rm1 = fmaxf(rm1, fmaxf(sacc[nf][2], sacc[nf][3]));
            }
            rm0 = fmaxf(rm0, __shfl_xor_sync(0xffffffffu, rm0, 1));
            rm0 = fmaxf(rm0, __shfl_xor_sync(0xffffffffu, rm0, 2));
            rm1 = fmaxf(rm1, __shfl_xor_sync(0xffffffffu, rm1, 1));
            rm1 = fmaxf(rm1, __shfl_xor_sync(0xffffffffu, rm1, 2));

            const float mn0 = fmaxf(m0, rm0);
            const float mn1 = fmaxf(m1, rm1);
            const float rs0 = exp2_fast(m0 - mn0);
            const float rs1 = exp2_fast(m1 - mn1);
            m0 = mn0; m1 = mn1;

            float sum0 = 0.f, sum1 = 0.f;
            #pragma unroll
            for (int nf = 0; nf < 8; nf++) {
                sacc[nf][0] = exp2_fast(sacc[nf][0] - mn0);
                sacc[nf][1] = exp2_fast(sacc[nf][1] - mn0);
                sacc[nf][2] = exp2_fast(sacc[nf][2] - mn1);
                sacc[nf][3] = exp2_fast(sacc[nf][3] - mn1);
                sum0 += sacc[nf][0] + sacc[nf][1];
                sum1 += sacc[nf][2] + sacc[nf][3];
            }
            sum0 += __shfl_xor_sync(0xffffffffu, sum0, 1);
            sum0 += __shfl_xor_sync(0xffffffffu, sum0, 2);
            sum1 += __shfl_xor_sync(0xffffffffu, sum1, 1);
            sum1 += __shfl_xor_sync(0xffffffffu, sum1, 2);
            l0 = l0 * rs0 + sum0;
            l1 = l1 * rs1 + sum1;

            #pragma unroll
            for (int nf = 0; nf < 8; nf++) {
                oacc[nf][0] *= rs0;
                oacc[nf][1] *= rs0;
                oacc[nf][2] *= rs1;
                oacc[nf][3] *= rs1;
            }

            const u32 vfb = Vbase + (sboff + lmF) * 4;
            #pragma unroll
            for (int g = 0; g < 4; g++) {
                u32 ph[4], pl[4];
                split_pack_f16(sacc[2 * g][0],     sacc[2 * g][1],     ph[0], pl[0]);
                split_pack_f16(sacc[2 * g][2],     sacc[2 * g][3],     ph[1], pl[1]);
                split_pack_f16(sacc[2 * g + 1][0], sacc[2 * g + 1][1], ph[2], pl[2]);
                split_pack_f16(sacc[2 * g + 1][2], sacc[2 * g + 1][3], ph[3], pl[3]);
                #pragma unroll
                for (int nfp = 0; nfp < 4; nfp++) {
                    u32 vf[4];
                    ldsm_x4(vf, vfb + (u32)(nfp * 16 * FKS + 8 * g) * 4);
                    mma_f16(oacc[2 * nfp],     ph, vf);
                    mma_f16(oacc[2 * nfp],     pl, vf);
                    mma_f16(oacc[2 * nfp + 1], ph, vf + 2);
                    mma_f16(oacc[2 * nfp + 1], pl, vf + 2);
                }
            }
        }
    }

    const float inv0 = 1.0f / l0;
    const float inv1 = 1.0f / l1;
    const int b = bh >> 4, h = bh & 15;
    #pragma unroll
    for (int nf = 0; nf < 8; nf++) {
        const int d = nf * 8 + 2 * c4;
        float2 v0 = make_float2(oacc[nf][0] * inv0, oacc[nf][1] * inv0);
        float2 v1 = make_float2(oacc[nf][2] * inv1, oacc[nf][3] * inv1);
        *(float2*)(g_o + ((size_t)(b * TSEQ) + row0) * DIM + h * HD + d) = v0;
        *(float2*)(g_o + ((size_t)(b * TSEQ) + row1) * DIM + h * HD + d) = v1;
    }
}

// ---------------------------------------------------------------------------
extern "C" void kernel_launch(void* const* d_in, const int* in_sizes, int n_in,
                              void* d_out, int out_size)
{
    const float* x      = (const float*)d_in[0];
    const float* w_qkv  = (const float*)d_in[1];
    const float* w_proj = (const float*)d_in[2];
    const float* b_proj = (const float*)d_in[3];
    float* out = (float*)d_out;

    float* o_p = nullptr;
    cudaGetSymbolAddress((void**)&o_p, g_o);
    u32 *xh, *xl, *oh, *ol, *wqh, *wph;
    cudaGetSymbolAddress((void**)&xh,  g_xh);
    cudaGetSymbolAddress((void**)&xl,  g_xl);
    cudaGetSymbolAddress((void**)&oh,  g_oh2);
    cudaGetSymbolAddress((void**)&ol,  g_ol2);
    cudaGetSymbolAddress((void**)&wqh, g_wqh);
    cudaGetSymbolAddress((void**)&wph, g_wph);

    cudaFuncSetAttribute(mma_gemm6,
                         cudaFuncAttributeMaxDynamicSharedMemorySize, G6_SMEM);

    // 0) trig table + operand prepasses
    trig_table<<<(TSEQ * 32 + 255) / 256, 256>>>();
    const int xpairs = TOKENS * DIM / 2;
    split_pairs_rows<<<(xpairs + 255) / 256, 256>>>(x, xh, xl, xpairs);
    pack_pairs_cols<<<((DIM / 2) * QKV_N + 255) / 256, 256>>>(w_qkv, wqh, QKV_N, DIM);
    pack_pairs_cols<<<((DIM / 2) * DIM + 255) / 256, 256>>>(w_proj, wph, DIM, DIM);

    // 1) qkv = x @ w_qkv -> g_q/g_k/g_v
    mma_gemm6<<<dim3(QKV_N / 128, TOKENS / 128), 256, G6_SMEM>>>(
        xh, xl, wqh, nullptr, nullptr, QKV_N, DIM, 1);

    // 2) rope + pack
    rope_split<<<(BHEADS * TSEQ * 32 + 255) / 256, 256>>>();

    // 3) V transpose + pack
    v_transpose<<<dim3(TSEQ / 64, BHEADS), 256>>>();

    // 4) flash attention (fp16 2-pass, ldmatrix)
    flash_mma<<<dim3(TSEQ / 128, BHEADS), 256>>>();

    // 5) out = g_o @ w_proj + b_proj
    split_pairs_rows<<<(xpairs + 255) / 256, 256>>>(o_p, oh, ol, xpairs);
    mma_gemm6<<<dim3(DIM / 128, TOKENS / 128), 256, G6_SMEM>>>(
        oh, ol, wph, out, b_proj, DIM, DIM, 0);
}

// round 13
// speedup vs baseline: 3.7467x; 1.0527x over previous
#include <cuda_runtime.h>
#include <cuda_fp16.h>
#include <stdint.h>
#include <math.h>

typedef unsigned int u32;

#define TOKENS 4096
#define DIM    1024
#define QKV_N  3072
#define NH     16
#define HD     64
#define TSEQ   2048
#define BHEADS 32
// 0.125 * log2(e)
#define SCALE2 0.18033688011112042f

// ---------------- global scratch ----------------
__device__ float g_q[BHEADS * TSEQ * HD];   // [bh][t][d] (pre-rope fp32)
__device__ float g_k[BHEADS * TSEQ * HD];
__device__ float g_v[BHEADS * TSEQ * HD];

__device__ float2 g_trig[TSEQ * 32];

// GEMM A operands: [M][K2] u32 (fp16 pairs along K), hi+lo split
__device__ u32 g_xh[TOKENS * DIM / 2],  g_xl[TOKENS * DIM / 2];
__device__ u32 g_oh2[TOKENS * DIM / 2], g_ol2[TOKENS * DIM / 2];
// GEMM B operands: [K2][N] u32 (fp16 pairs along K), rounded single
__device__ u32 g_wqh[DIM / 2 * QKV_N];
__device__ u32 g_wph[DIM / 2 * DIM];

// flash operands: Q split hi/lo, K/V rounded single (fp16 pairs)
__device__ u32 g_qh[BHEADS * TSEQ * 32], g_ql[BHEADS * TSEQ * 32];
__device__ u32 g_kh[BHEADS * TSEQ * 32];
__device__ u32 g_vth[BHEADS * HD * (TSEQ / 2)];

// ---------------- helpers ----------------
__device__ __forceinline__ void mma_f16(float c[4],
                                        const u32 a[4], const u32 b[2])
{
    asm volatile(
        "mma.sync.aligned.m16n8k16.row.col.f32.f16.f16.f32 "
        "{%0,%1,%2,%3}, {%4,%5,%6,%7}, {%8,%9}, {%0,%1,%2,%3};"
        : "+f"(c[0]), "+f"(c[1]), "+f"(c[2]), "+f"(c[3])
        : "r"(a[0]), "r"(a[1]), "r"(a[2]), "r"(a[3]),
          "r"(b[0]), "r"(b[1]));
}

__device__ __forceinline__ void ldsm_x4(u32 r[4], u32 saddr)
{
    asm volatile(
        "ldmatrix.sync.aligned.m8n8.x4.shared.b16 {%0,%1,%2,%3}, [%4];"
        : "=r"(r[0]), "=r"(r[1]), "=r"(r[2]), "=r"(r[3]) : "r"(saddr));
}

__device__ __forceinline__ void split_pack_f16(float x0, float x1,
                                               u32& hi, u32& lo)
{
    __half2 H = __floats2half2_rn(x0, x1);
    float2 hf = __half22float2(H);
    __half2 L = __floats2half2_rn(x0 - hf.x, x1 - hf.y);
    hi = *(u32*)&H;
    lo = *(u32*)&L;
}

__device__ __forceinline__ u32 pack_f16(float x0, float x1)
{
    __half2 H = __floats2half2_rn(x0, x1);
    return *(u32*)&H;
}

// FFMA-only exp2 (no MUFU)
__device__ __forceinline__ float exp2_fast(float x)
{
    x = fmaxf(x, -60.0f);
    float t  = __fadd_rn(x, 12582912.0f);
    int   n  = __float_as_int(t) << 23;
    float ni = __fadd_rn(t, -12582912.0f);
    float r  = __fadd_rn(x, -ni);
    float p  = 1.3333558e-3f;
    p = fmaf(p, r, 9.6181291e-3f);
    p = fmaf(p, r, 5.5504109e-2f);
    p = fmaf(p, r, 2.4022651e-1f);
    p = fmaf(p, r, 6.9314718e-1f);
    p = fmaf(p, r, 1.0f);
    return __int_as_float(__float_as_int(p) + n);
}

__device__ __forceinline__ void cp16(u32* smem_dst, const u32* gsrc)
{
    unsigned d = (unsigned)__cvta_generic_to_shared(smem_dst);
    asm volatile("cp.async.cg.shared.global [%0], [%1], 16;" :: "r"(d), "l"(gsrc));
}

// ---------------- prepass kernels ----------------
__global__ __launch_bounds__(256)
void split_pairs_rows(const float* __restrict__ src, u32* __restrict__ hi,
                      u32* __restrict__ lo, int npairs)
{
    int i = blockIdx.x * 256 + threadIdx.x;
    if (i >= npairs) return;
    float2 v = ((const float2*)src)[i];
    split_pack_f16(v.x, v.y, hi[i], lo[i]);
}

__global__ __launch_bounds__(256)
void pack_pairs_cols(const float* __restrict__ B, u32* __restrict__ hi,
                     int N, int K)
{
    int i = blockIdx.x * 256 + threadIdx.x;
    int K2 = K >> 1;
    if (i >= K2 * N) return;
    int k2 = i / N, n = i - k2 * N;
    hi[i] = pack_f16(B[(size_t)(2 * k2) * N + n],
                     B[(size_t)(2 * k2 + 1) * N + n]);
}

// ---------------------------------------------------------------------------
// mma_gemm6: fp16 A-split 2-pass GEMM, 3-stage cp.async, ldmatrix A-frags.
// ---------------------------------------------------------------------------
#define A_ST  (128 * 20)
#define B_ST  (16 * 136)
#define STG_U32 (2 * A_ST + B_ST)
#define G6_SMEM (3 * STG_U32 * 4)

__global__ __launch_bounds__(256, 2)
void mma_gemm6(const u32* __restrict__ Agh, const u32* __restrict__ Agl,
               const u32* __restrict__ Bgh,
               float* __restrict__ C, const float* __restrict__ bias,
               int N, int K, int epi)
{
    extern __shared__ u32 sm6[];

    const int tid  = threadIdx.x;
    const int wid  = tid >> 5;
    const int lane = tid & 31;
    const int r8   = lane >> 2;
    const int c4   = lane & 3;
    const int grp  = lane >> 3;
    const int wtn  = lane & 7;
    const int wm   = (wid >> 2) * 64;
    const int wn   = (wid & 3) * 32;
    const int brow = blockIdx.y, bcol = blockIdx.x;
    const int K2   = K >> 1;

    const u32 smbase = (u32)__cvta_generic_to_shared(sm6);
    const u32 lmA = (u32)(((grp & 1) * 8 + wtn) * 20 + (grp >> 1) * 4);

    const int ar  = tid & 127;
    const int acb = (tid >> 7) * 8;
    const u32* Aph = Agh + (size_t)(brow * 128 + ar) * K2 + acb;
    const u32* Apl = Agl + (size_t)(brow * 128 + ar) * K2 + acb;
    const int bk  = tid >> 4;
    const int bnc = (tid & 15) * 8;
    const u32* Bph = Bgh + (size_t)bk * N + bcol * 128 + bnc;

    float acc[4][4][4];
    #pragma unroll
    for (int i = 0; i < 4; i++)
        #pragma unroll
        for (int j = 0; j < 4; j++)
            #pragma unroll
            for (int r = 0; r < 4; r++) acc[i][j][r] = 0.f;

    auto issue = [&](int k2base, int s) {
        u32* st = sm6 + s * STG_U32;
        u32* aH = st + ar * 20 + acb;
        u32* aL = st + A_ST + ar * 20 + acb;
        cp16(aH,     Aph + k2base);
        cp16(aH + 4, Aph + k2base + 4);
        cp16(aL,     Apl + k2base);
        cp16(aL + 4, Apl + k2base + 4);
        u32* bH = st + 2 * A_ST + bk * 136 + bnc;
        cp16(bH,     Bph + (size_t)k2base * N);
        cp16(bH + 4, Bph + (size_t)k2base * N + 4);
        asm volatile("cp.async.commit_group;");
    };

    issue(0, 0);
    issue(16, 1);

    const int nst = K2 >> 4;
    int s = 0;
    for (int ks = 0; ks < nst; ks++) {
        asm volatile("cp.async.wait_group 1;");
        __syncthreads();
        if (ks + 2 < nst) {
            int s2 = s + 2; if (s2 >= 3) s2 -= 3;
            issue((ks + 2) * 16, s2);
        } else {
            asm volatile("cp.async.commit_group;");
        }

        const u32 stoff = (u32)(s * STG_U32);
        const u32 aHb = smbase + (stoff + lmA + wm * 20) * 4;
        const u32 aLb = aHb + A_ST * 4;
        const u32* bH = sm6 + stoff + 2 * A_ST;

        #pragma unroll
        for (int kk = 0; kk < 2; kk++) {
            const int kc = kk * 8 + c4;
            u32 bh[4][2];
            #pragma unroll
            for (int nf = 0; nf < 4; nf++) {
                const int n = wn + nf * 8 + r8;
                bh[nf][0] = bH[kc * 136 + n];
                bh[nf][1] = bH[(kc + 4) * 136 + n];
            }
            #pragma unroll
            for (int mf = 0; mf < 4; mf++) {
                u32 ah[4], al[4];
                const u32 moff = (u32)(mf * 16 * 20 + kk * 8) * 4;
                ldsm_x4(ah, aHb + moff);
                ldsm_x4(al, aLb + moff);
                #pragma unroll
                for (int nf = 0; nf < 4; nf++) {
                    mma_f16(acc[mf][nf], ah, bh[nf]);
                    mma_f16(acc[mf][nf], al, bh[nf]);
                }
            }
        }
        if (++s >= 3) s -= 3;
    }

    if (!epi) {
        #pragma unroll
        for (int nf = 0; nf < 4; nf++) {
            const int cg = bcol * 128 + wn + nf * 8 + c4 * 2;
            float bx = bias ? bias[cg]     : 0.f;
            float by = bias ? bias[cg + 1] : 0.f;
            #pragma unroll
            for (int mf = 0; mf < 4; mf++) {
                const int rg = brow * 128 + wm + mf * 16 + r8;
                float2 v0 = make_float2(acc[mf][nf][0] + bx, acc[mf][nf][1] + by);
                float2 v1 = make_float2(acc[mf][nf][2] + bx, acc[mf][nf][3] + by);
                *(float2*)(C + (size_t)rg * N + cg)       = v0;
                *(float2*)(C + (size_t)(rg + 8) * N + cg) = v1;
            }
        }
    } else {
        #pragma unroll
        for (int nf = 0; nf < 4; nf++) {
            const int n_g   = bcol * 128 + wn + nf * 8 + c4 * 2;
            const int which = n_g >> 10;
            const int rmod  = n_g & 1023;
            const int h     = rmod >> 6;
            const int d     = rmod & 63;
            float* base = (which == 0) ? g_q : (which == 1) ? g_k : g_v;
            #pragma unroll
            for (int mf = 0; mf < 4; mf++) {
                const int m_g0 = brow * 128 + wm + mf * 16 + r8;
                #pragma unroll
                for (int half = 0; half < 2; half++) {
                    const int m_g = m_g0 + half * 8;
                    const int b   = m_g >> 11;
                    const int t   = m_g & 2047;
                    float2 v = make_float2(acc[mf][nf][half * 2],
                                           acc[mf][nf][half * 2 + 1]);
                    *(float2*)(base + (((size_t)(b * 16 + h) * TSEQ + t) * HD + d)) = v;
                }
            }
        }
    }
}

// ---------------------------------------------------------------------------
__global__ __launch_bounds__(256)
void trig_table()
{
    int idx = blockIdx.x * 256 + threadIdx.x;
    if (idx >= TSEQ * 32) return;
    int t = idx >> 5, i = idx & 31;
    float freq = expf(-9.210340371976184f * (float)i * (1.0f / 32.0f));
    float ang = (float)t * freq;
    float s, c;
    sincosf(ang, &s, &c);
    g_trig[idx] = make_float2(s, c);
}

// ---------------------------------------------------------------------------
__global__ __launch_bounds__(256)
void rope_split()
{
    int gw   = (blockIdx.x * 256 + threadIdx.x) >> 5;
    int lane = threadIdx.x & 31;
    if (gw >= BHEADS * TSEQ) return;
    int bh = gw >> 11;
    int t  = gw & 2047;

    float2 sc = g_trig[t * 32 + lane];
    float s = sc.x, c = sc.y;

    size_t off = ((size_t)bh * TSEQ + t) * HD;

    float q1 = g_q[off + lane], q2 = g_q[off + lane + 32];
    float qa = (q1 * c - q2 * s) * SCALE2;
    float qb = (q1 * s + q2 * c) * SCALE2;

    float k1 = g_k[off + lane], k2 = g_k[off + lane + 32];
    float ka = k1 * c - k2 * s;
    float kb = k1 * s + k2 * c;

    int src = (2 * lane) & 31;
    float qa0 = __shfl_sync(0xffffffffu, qa, src);
    float qa1 = __shfl_sync(0xffffffffu, qa, src + 1);
    float qb0 = __shfl_sync(0xffffffffu, qb, src);
    float qb1 = __shfl_sync(0xffffffffu, qb, src + 1);
    float ka0 = __shfl_sync(0xffffffffu, ka, src);
    float ka1 = __shfl_sync(0xffffffffu, ka, src + 1);
    float kb0 = __shfl_sync(0xffffffffu, kb, src);
    float kb1 = __shfl_sync(0xffffffffu, kb, src + 1);

    float e0 = (lane < 16) ? qa0 : qb0;
    float e1 = (lane < 16) ? qa1 : qb1;
    u32 hi, lo;
    split_pack_f16(e0, e1, hi, lo);
    size_t po = ((size_t)bh * TSEQ + t) * 32 + lane;
    g_qh[po] = hi;
    g_ql[po] = lo;

    e0 = (lane < 16) ? ka0 : kb0;
    e1 = (lane < 16) ? ka1 : kb1;
    g_kh[po] = pack_f16(e0, e1);
}

// ---------------------------------------------------------------------------
__global__ __launch_bounds__(256)
void v_transpose()
{
    __shared__ float sv[64][65];
    const int bh = blockIdx.y, tb = blockIdx.x;
    const int tid = threadIdx.x;

    {
        int r = tid >> 2, cb = (tid & 3) * 16;
        const float* vp = g_v + ((size_t)bh * TSEQ + tb * 64 + r) * HD + cb;
        #pragma unroll
        for (int i = 0; i < 16; i += 4) {
            float4 v = *(const float4*)(vp + i);
            sv[r][cb + i + 0] = v.x;
            sv[r][cb + i + 1] = v.y;
            sv[r][cb + i + 2] = v.z;
            sv[r][cb + i + 3] = v.w;
        }
    }
    __syncthreads();

    int t2 = tid & 31, dbase = (tid >> 5) * 8;
    #pragma unroll
    for (int i = 0; i < 8; i++) {
        int d = dbase + i;
        size_t o = ((size_t)bh * HD + d) * (TSEQ / 2) + tb * 32 + t2;
        g_vth[o] = pack_f16(sv[2 * t2][d], sv[2 * t2 + 1][d]);
    }
}

// ---------------------------------------------------------------------------
// Flash attention: fp16 (Q split 2-pass S, P single-pass PV), ldmatrix,
// cp.async double-buffered, exp2 softmax. Epilogue writes split o directly.
// ---------------------------------------------------------------------------
#define FKS  36
#define FTILE (64 * FKS)

__global__ __launch_bounds__(256)
void flash_mma()
{
    __shared__ u32 Ksh[2 * FTILE];
    __shared__ u32 Vsh[2 * FTILE];

    const int bh   = blockIdx.y;
    const int qblk = gridDim.x - 1 - blockIdx.x;
    const int q0   = qblk * 128;

    const int tid  = threadIdx.x;
    const int w    = tid >> 5;
    const int lane = tid & 31;
    const int r8   = lane >> 2;
    const int c4   = lane & 3;
    const int grp  = lane >> 3;
    const int wtn  = lane & 7;

    const u32 Kbase = (u32)__cvta_generic_to_shared(Ksh);
    const u32 Vbase = (u32)__cvta_generic_to_shared(Vsh);
    const u32 lmF = (u32)(((grp >> 1) * 8 + wtn) * FKS + (grp & 1) * 4);

    u32 qh[4][4], ql[4][4];
    {
        const u32* Qh = g_qh + ((size_t)bh * TSEQ + q0 + w * 16) * 32;
        const u32* Ql = g_ql + ((size_t)bh * TSEQ + q0 + w * 16) * 32;
        #pragma unroll
        for (int g = 0; g < 4; g++) {
            qh[g][0] = Qh[(size_t)r8 * 32 + 8 * g + c4];
            qh[g][1] = Qh[(size_t)(r8 + 8) * 32 + 8 * g + c4];
            qh[g][2] = Qh[(size_t)r8 * 32 + 8 * g + c4 + 4];
            qh[g][3] = Qh[(size_t)(r8 + 8) * 32 + 8 * g + c4 + 4];
            ql[g][0] = Ql[(size_t)r8 * 32 + 8 * g + c4];
            ql[g][1] = Ql[(size_t)(r8 + 8) * 32 + 8 * g + c4];
            ql[g][2] = Ql[(size_t)r8 * 32 + 8 * g + c4 + 4];
            ql[g][3] = Ql[(size_t)(r8 + 8) * 32 + 8 * g + c4 + 4];
        }
    }

    float oacc[8][4];
    #pragma unroll
    for (int i = 0; i < 8; i++)
        #pragma unroll
        for (int j = 0; j < 4; j++) oacc[i][j] = 0.f;
    float m0 = -1e30f, m1 = -1e30f, l0 = 0.f, l1 = 0.f;

    const int row0 = q0 + w * 16 + r8;
    const int row1 = row0 + 8;

    const u32* Kgh = g_kh + (size_t)bh * TSEQ * 32;
    const u32* Vgh = g_vth + (size_t)bh * HD * (TSEQ / 2);

    const int lr = tid >> 2, lcb = (tid & 3) * 8;

    auto fissue = [&](int tile, int s) {
        const int k0 = tile * 64;
        const u32* kh = Kgh + (size_t)(k0 + lr) * 32 + lcb;
        const u32* vh = Vgh + (size_t)lr * (TSEQ / 2) + (k0 >> 1) + lcb;
        u32* dk = Ksh + s * FTILE + lr * FKS + lcb;
        u32* dv = Vsh + s * FTILE + lr * FKS + lcb;
        cp16(dk,     kh);
        cp16(dk + 4, kh + 4);
        cp16(dv,     vh);
        cp16(dv + 4, vh + 4);
        asm volatile("cp.async.commit_group;");
    };

    const int ntiles = 2 * qblk + 2;
    fissue(0, 0);

    for (int tile = 0; tile < ntiles; tile++) {
        asm volatile("cp.async.wait_group 0;");
        __syncthreads();
        if (tile + 1 < ntiles) fissue(tile + 1, (tile + 1) & 1);

        const u32 sboff = (u32)((tile & 1) * FTILE);
        const int k0 = tile * 64;

        const bool active = (k0 <= q0 + w * 16 + 15);
        if (active) {
            float sacc[8][4];
            #pragma unroll
            for (int i = 0; i < 8; i++)
                #pragma unroll
                for (int j = 0; j < 4; j++) sacc[i][j] = 0.f;

            const u32 kfb = Kbase + (sboff + lmF) * 4;
            #pragma unroll
            for (int g = 0; g < 4; g++) {
                #pragma unroll
                for (int nfp = 0; nfp < 4; nfp++) {
                    u32 kf[4];
                    ldsm_x4(kf, kfb + (u32)(nfp * 16 * FKS + 8 * g) * 4);
                    mma_f16(sacc[2 * nfp],     qh[g], kf);
                    mma_f16(sacc[2 * nfp],     ql[g], kf);
                    mma_f16(sacc[2 * nfp + 1], qh[g], kf + 2);
                    mma_f16(sacc[2 * nfp + 1], ql[g], kf + 2);
                }
            }

            if (k0 + 63 > row0) {
                #pragma unroll
                for (int nf = 0; nf < 8; nf++) {
                    const int n0 = k0 + nf * 8 + 2 * c4;
                    if (n0 > row0)     sacc[nf][0] = -1e30f;
                    if (n0 + 1 > row0) sacc[nf][1] = -1e30f;
                    if (n0 > row1)     sacc[nf][2] = -1e30f;
                    if (n0 + 1 > row1) sacc[nf][3] = -1e30f;
                }
            }

            float rm0 = -1e30f, rm1 = -1e30f;
            #pragma unroll
            for (int nf = 0; nf < 8; nf++) {
                rm0 = fmaxf(rm0, fmaxf(sacc[nf][0], sacc[nf][1]));
                rm1 = fmaxf(rm1, fmaxf(sacc[nf][2], sacc[nf][3]));
            }
            rm0 = fmaxf(rm0, __shfl_xor_sync(0xffffffffu, rm0, 1));
            rm0 = fmaxf(rm0, __shfl_xor_sync(0xffffffffu, rm0, 2));
            rm1 = fmaxf(rm1, __shfl_xor_sync(0xffffffffu, rm1, 1));
            rm1 = fmaxf(rm1, __shfl_xor_sync(0xffffffffu, rm1, 2));

            const float mn0 = fmaxf(m0, rm0);
            const float mn1 = fmaxf(m1, rm1);
            const float rs0 = exp2_fast(m0 - mn0);
            const float rs1 = exp2_fast(m1 - mn1);
            m0 = mn0; m1 = mn1;

            float sum0 = 0.f, sum1 = 0.f;
            #pragma unroll
            for (int nf = 0; nf < 8; nf++) {
                sacc[nf][0] = exp2_fast(sacc[nf][0] - mn0);
                sacc[nf][1] = exp2_fast(sacc[nf][1] - mn0);
                sacc[nf][2] = exp2_fast(sacc[nf][2] - mn1);
                sacc[nf][3] = exp2_fast(sacc[nf][3] - mn1);
                sum0 += sacc[nf][0] + sacc[nf][1];
                sum1 += sacc[nf][2] + sacc[nf][3];
            }
            sum0 += __shfl_xor_sync(0xffffffffu, sum0, 1);
            sum0 += __shfl_xor_sync(0xffffffffu, sum0, 2);
            sum1 += __shfl_xor_sync(0xffffffffu, sum1, 1);
            sum1 += __shfl_xor_sync(0xffffffffu, sum1, 2);
            l0 = l0 * rs0 + sum0;
            l1 = l1 * rs1 + sum1;

            #pragma unroll
            for (int nf = 0; nf < 8; nf++) {
                oacc[nf][0] *= rs0;
                oacc[nf][1] *= rs0;
                oacc[nf][2] *= rs1;
                oacc[nf][3] *= rs1;
            }

            const u32 vfb = Vbase + (sboff + lmF) * 4;
            #pragma unroll
            for (int g = 0; g < 4; g++) {
                u32 ph[4];
                ph[0] = pack_f16(sacc[2 * g][0],     sacc[2 * g][1]);
                ph[1] = pack_f16(sacc[2 * g][2],     sacc[2 * g][3]);
                ph[2] = pack_f16(sacc[2 * g + 1][0], sacc[2 * g + 1][1]);
                ph[3] = pack_f16(sacc[2 * g + 1][2], sacc[2 * g + 1][3]);
                #pragma unroll
                for (int nfp = 0; nfp < 4; nfp++) {
                    u32 vf[4];
                    ldsm_x4(vf, vfb + (u32)(nfp * 16 * FKS + 8 * g) * 4);
                    mma_f16(oacc[2 * nfp],     ph, vf);
                    mma_f16(oacc[2 * nfp + 1], ph, vf + 2);
                }
            }
        }
    }

    // epilogue: normalize and write split fp16 o directly (proj A-operand)
    const float inv0 = 1.0f / l0;
    const float inv1 = 1.0f / l1;
    const int b = bh >> 4, h = bh & 15;
    #pragma unroll
    for (int nf = 0; nf < 8; nf++) {
        const size_t i0 = ((size_t)(b * TSEQ) + row0) * 512 + h * 32 + nf * 4 + c4;
        const size_t i1 = ((size_t)(b * TSEQ) + row1) * 512 + h * 32 + nf * 4 + c4;
        split_pack_f16(oacc[nf][0] * inv0, oacc[nf][1] * inv0, g_oh2[i0], g_ol2[i0]);
        split_pack_f16(oacc[nf][2] * inv1, oacc[nf][3] * inv1, g_oh2[i1], g_ol2[i1]);
    }
}

// ---------------------------------------------------------------------------
extern "C" void kernel_launch(void* const* d_in, const int* in_sizes, int n_in,
                              void* d_out, int out_size)
{
    const float* x      = (const float*)d_in[0];
    const float* w_qkv  = (const float*)d_in[1];
    const float* w_proj = (const float*)d_in[2];
    const float* b_proj = (const float*)d_in[3];
    float* out = (float*)d_out;

    u32 *xh, *xl, *oh, *ol, *wqh, *wph;
    cudaGetSymbolAddress((void**)&xh,  g_xh);
    cudaGetSymbolAddress((void**)&xl,  g_xl);
    cudaGetSymbolAddress((void**)&oh,  g_oh2);
    cudaGetSymbolAddress((void**)&ol,  g_ol2);
    cudaGetSymbolAddress((void**)&wqh, g_wqh);
    cudaGetSymbolAddress((void**)&wph, g_wph);

    cudaFuncSetAttribute(mma_gemm6,
                         cudaFuncAttributeMaxDynamicSharedMemorySize, G6_SMEM);

    // 0) trig table + operand prepasses
    trig_table<<<(TSEQ * 32 + 255) / 256, 256>>>();
    const int xpairs = TOKENS * DIM / 2;
    split_pairs_rows<<<(xpairs + 255) / 256, 256>>>(x, xh, xl, xpairs);
    pack_pairs_cols<<<((DIM / 2) * QKV_N + 255) / 256, 256>>>(w_qkv, wqh, QKV_N, DIM);
    pack_pairs_cols<<<((DIM / 2) * DIM + 255) / 256, 256>>>(w_proj, wph, DIM, DIM);

    // 1) qkv = x @ w_qkv -> g_q/g_k/g_v
    mma_gemm6<<<dim3(QKV_N / 128, TOKENS / 128), 256, G6_SMEM>>>(
        xh, xl, wqh, nullptr, nullptr, QKV_N, DIM, 1);

    // 2) rope + pack
    rope_split<<<(BHEADS * TSEQ * 32 + 255) / 256, 256>>>();

    // 3) V transpose + pack
    v_transpose<<<dim3(TSEQ / 64, BHEADS), 256>>>();

    // 4) flash attention (writes split o directly)
    flash_mma<<<dim3(TSEQ / 128, BHEADS), 256>>>();

    // 5) out = o @ w_proj + b_proj
    mma_gemm6<<<dim3(DIM / 128, TOKENS / 128), 256, G6_SMEM>>>(
        oh, ol, wph, out, b_proj, DIM, DIM, 0);
}